// round 8
// baseline (speedup 1.0000x reference)
#include <cuda_runtime.h>
#include <cuda_bf16.h>
#include <math.h>
#include <stdint.h>

// Problem constants
#define BATCH 4
#define SEQ_N 4096
#define SEQ_M 256
#define DIM 1024
#define CTX_DIM 768
#define HEADS 16
#define HD 64
#define ROWS_X (BATCH * SEQ_N)      // 16384
#define ROWS_C (BATCH * SEQ_M)      // 1024

// Scratch (device globals)
__device__ __nv_bfloat16 g_Ah[ROWS_X * DIM];
__device__ __nv_bfloat16 g_Al[ROWS_X * DIM];
__device__ __nv_bfloat16 g_Ch[ROWS_C * CTX_DIM];
__device__ __nv_bfloat16 g_Cl[ROWS_C * CTX_DIM];
__device__ __nv_bfloat16 g_Bh[DIM * DIM];
__device__ __nv_bfloat16 g_Bl[DIM * DIM];
__device__ __nv_bfloat16 g_Qh[ROWS_X * DIM];
__device__ __nv_bfloat16 g_Ql[ROWS_X * DIM];
__device__ __nv_bfloat16 g_Kh[ROWS_C * DIM];
__device__ __nv_bfloat16 g_Kl[ROWS_C * DIM];
__device__ __nv_bfloat16 g_Vh[ROWS_C * DIM];
__device__ __nv_bfloat16 g_Vl[ROWS_C * DIM];

// ---------------------------------------------------------------------------
// PTX helpers (sm_80+ portable)
// ---------------------------------------------------------------------------
__device__ __forceinline__ uint32_t smem_u32(const void* p) {
    uint32_t a;
    asm("{ .reg .u64 t; cvta.to.shared.u64 t, %1; cvt.u32.u64 %0, t; }" : "=r"(a) : "l"(p));
    return a;
}
#define CP_ASYNC16(dst, src) \
    asm volatile("cp.async.cg.shared.global [%0], [%1], 16;" :: "r"(dst), "l"(src))
#define CP_COMMIT() asm volatile("cp.async.commit_group;" ::: "memory")
#define CP_WAIT(n)  asm volatile("cp.async.wait_group %0;" :: "n"(n) : "memory")

#define LDM_X4(r0, r1, r2, r3, a) \
    asm volatile("ldmatrix.sync.aligned.m8n8.x4.shared.b16 {%0,%1,%2,%3}, [%4];" \
                 : "=r"(r0), "=r"(r1), "=r"(r2), "=r"(r3) : "r"(a))
#define LDM_X4T(r0, r1, r2, r3, a) \
    asm volatile("ldmatrix.sync.aligned.m8n8.x4.trans.shared.b16 {%0,%1,%2,%3}, [%4];" \
                 : "=r"(r0), "=r"(r1), "=r"(r2), "=r"(r3) : "r"(a))

#define MMA_BF16(d, a, b) \
    asm volatile("mma.sync.aligned.m16n8k16.row.col.f32.bf16.bf16.f32 " \
                 "{%0,%1,%2,%3},{%4,%5,%6,%7},{%8,%9},{%0,%1,%2,%3};" \
                 : "+f"((d)[0]), "+f"((d)[1]), "+f"((d)[2]), "+f"((d)[3]) \
                 : "r"((a)[0]), "r"((a)[1]), "r"((a)[2]), "r"((a)[3]), \
                   "r"((b)[0]), "r"((b)[1]))

__device__ __forceinline__ void split2(float x, float y, uint32_t& h, uint32_t& l) {
    __nv_bfloat162 hb = __float22bfloat162_rn(make_float2(x, y));
    float2 hf = __bfloat1622float2(hb);
    __nv_bfloat162 lb = __float22bfloat162_rn(make_float2(x - hf.x, y - hf.y));
    h = *(uint32_t*)&hb;
    l = *(uint32_t*)&lb;
}

// ---------------------------------------------------------------------------
// fp32 -> bf16 hi/lo split
// ---------------------------------------------------------------------------
__global__ void split_kernel(const float* __restrict__ X, __nv_bfloat16* __restrict__ Xh,
                             __nv_bfloat16* __restrict__ Xl, int n4)
{
    int i = blockIdx.x * blockDim.x + threadIdx.x;
    if (i >= n4) return;
    float4 v = ((const float4*)X)[i];
    float a[4] = {v.x, v.y, v.z, v.w};
    __nv_bfloat16 h[4], l[4];
    #pragma unroll
    for (int j = 0; j < 4; j++) {
        h[j] = __float2bfloat16(a[j]);
        l[j] = __float2bfloat16(a[j] - __bfloat162float(h[j]));
    }
    __nv_bfloat162* Hp = (__nv_bfloat162*)(Xh + 4 * (size_t)i);
    __nv_bfloat162* Lp = (__nv_bfloat162*)(Xl + 4 * (size_t)i);
    Hp[0] = __nv_bfloat162(h[0], h[1]); Hp[1] = __nv_bfloat162(h[2], h[3]);
    Lp[0] = __nv_bfloat162(l[0], l[1]); Lp[1] = __nv_bfloat162(l[2], l[3]);
}

// ---------------------------------------------------------------------------
// W[K][N] -> Th/Tl[N][K] bf16 hi/lo (transpose + split)
// ---------------------------------------------------------------------------
__global__ void transpose_split_kernel(const float* __restrict__ W, __nv_bfloat16* __restrict__ Th,
                                       __nv_bfloat16* __restrict__ Tl, int K, int N)
{
    __shared__ float tile[32][33];
    int n0 = blockIdx.x * 32, k0 = blockIdx.y * 32;
    int tx = threadIdx.x, ty = threadIdx.y;
    #pragma unroll
    for (int j = ty; j < 32; j += 8)
        tile[j][tx] = W[(size_t)(k0 + j) * N + n0 + tx];
    __syncthreads();
    #pragma unroll
    for (int j = ty; j < 32; j += 8) {
        float v = tile[tx][j];
        __nv_bfloat16 h = __float2bfloat16(v);
        __nv_bfloat16 l = __float2bfloat16(v - __bfloat162float(h));
        size_t o = (size_t)(n0 + j) * K + k0 + tx;
        Th[o] = h; Tl[o] = l;
    }
}

// ---------------------------------------------------------------------------
// HMMA bf16-split GEMM: 128x256x32 CTA tile, 8 warps (2x4) of 64x64,
// 3-stage cp.async pipeline. SPLIT=0: fp32 out. SPLIT=1: bf16 hi/lo out.
// ---------------------------------------------------------------------------
#define BM 128
#define BN 256
#define BK 32
#define PITCH 80
#define TILE_A (128 * PITCH)        // 10240
#define TILE_BB (256 * PITCH)       // 20480
#define STAGE  (2 * TILE_A + 2 * TILE_BB)   // 61440
#define GEMM_SMEM (3 * STAGE)               // 184320

template<int SPLIT>
__global__ void __launch_bounds__(256, 1)
gemm_hmma_kernel(const __nv_bfloat16* __restrict__ Ah, const __nv_bfloat16* __restrict__ Al,
                 const __nv_bfloat16* __restrict__ Bh, const __nv_bfloat16* __restrict__ Bl,
                 float* __restrict__ C, __nv_bfloat16* __restrict__ Ch,
                 __nv_bfloat16* __restrict__ Cl, int K)
{
    extern __shared__ __align__(128) char sm[];
    const uint32_t sb = smem_u32(sm);
    const int t = threadIdx.x, wid = t >> 5, lane = t & 31;
    const int m0 = blockIdx.y * BM, n0 = blockIdx.x * BN;
    const int NC = K / BK;
    const int wr = wid & 1, wc = wid >> 1;   // 2 x 4 warp grid, 64x64 tiles

    const int g = lane >> 3, lrw = lane & 7;
    const uint32_t a_off = (uint32_t)(((g & 1) * 8 + lrw) * PITCH + (g >> 1) * 16);
    const uint32_t b_off = (uint32_t)(((g >> 1) * 8 + lrw) * PITCH + (g & 1) * 16);

    float acc[4][8][4];
    #pragma unroll
    for (int mt = 0; mt < 4; mt++)
        #pragma unroll
        for (int ng = 0; ng < 8; ng++)
            #pragma unroll
            for (int q = 0; q < 4; q++) acc[mt][ng][q] = 0.0f;

    auto issue = [&](int c) {
        const uint32_t stg = sb + (uint32_t)(c % 3) * STAGE;
        const int kt = c * BK;
        #pragma unroll
        for (int i = 0; i < 2; i++) {
            int idx = t + i * 256;                 // < 512 : A 128 rows x 4 chunks
            int r = idx >> 2, ch = idx & 3;
            uint32_t doff = (uint32_t)(r * PITCH + ch * 16);
            size_t src = (size_t)(m0 + r) * K + kt + ch * 8;
            CP_ASYNC16(stg + doff,          Ah + src);
            CP_ASYNC16(stg + TILE_A + doff, Al + src);
        }
        #pragma unroll
        for (int i = 0; i < 4; i++) {
            int idx = t + i * 256;                 // < 1024 : B 256 rows x 4 chunks
            int r = idx >> 2, ch = idx & 3;
            uint32_t doff = (uint32_t)(r * PITCH + ch * 16);
            size_t src = (size_t)(n0 + r) * K + kt + ch * 8;
            CP_ASYNC16(stg + 2 * TILE_A + doff,           Bh + src);
            CP_ASYNC16(stg + 2 * TILE_A + TILE_BB + doff, Bl + src);
        }
        CP_COMMIT();
    };

    issue(0);
    issue(1);

    for (int c = 0; c < NC; c++) {
        if (c + 1 < NC) CP_WAIT(1);
        else            CP_WAIT(0);
        __syncthreads();
        if (c + 2 < NC) issue(c + 2);

        const uint32_t stg = sb + (uint32_t)(c % 3) * STAGE;
        const uint32_t aH = stg + (uint32_t)(wr * 64) * PITCH;
        const uint32_t aL = aH + TILE_A;
        const uint32_t bH = stg + 2 * TILE_A + (uint32_t)(wc * 64) * PITCH;
        const uint32_t bL = bH + TILE_BB;

        #pragma unroll
        for (int ks = 0; ks < 2; ks++) {
            const uint32_t kb = (uint32_t)(ks * 32);
            uint32_t fAh[4][4], fAl[4][4];
            #pragma unroll
            for (int mt = 0; mt < 4; mt++) {
                LDM_X4(fAh[mt][0], fAh[mt][1], fAh[mt][2], fAh[mt][3],
                       aH + (uint32_t)(mt * 16) * PITCH + kb + a_off);
                LDM_X4(fAl[mt][0], fAl[mt][1], fAl[mt][2], fAl[mt][3],
                       aL + (uint32_t)(mt * 16) * PITCH + kb + a_off);
            }
            #pragma unroll
            for (int nb = 0; nb < 4; nb++) {
                uint32_t h0, h1, h2, h3, l0, l1, l2, l3;
                LDM_X4(h0, h1, h2, h3, bH + (uint32_t)(nb * 16) * PITCH + kb + b_off);
                LDM_X4(l0, l1, l2, l3, bL + (uint32_t)(nb * 16) * PITCH + kb + b_off);
                uint32_t bh0[2] = {h0, h1}, bh1[2] = {h2, h3};
                uint32_t bl0[2] = {l0, l1}, bl1[2] = {l2, l3};
                #pragma unroll
                for (int mt = 0; mt < 4; mt++) {
                    MMA_BF16(acc[mt][nb * 2],     fAh[mt], bh0);
                    MMA_BF16(acc[mt][nb * 2],     fAh[mt], bl0);
                    MMA_BF16(acc[mt][nb * 2],     fAl[mt], bh0);
                    MMA_BF16(acc[mt][nb * 2 + 1], fAh[mt], bh1);
                    MMA_BF16(acc[mt][nb * 2 + 1], fAh[mt], bl1);
                    MMA_BF16(acc[mt][nb * 2 + 1], fAl[mt], bh1);
                }
            }
        }
        __syncthreads();
    }

    const int row0 = m0 + wr * 64 + lane / 4;
    const int colw = wc * 64 + (lane % 4) * 2;
    #pragma unroll
    for (int mt = 0; mt < 4; mt++) {
        #pragma unroll
        for (int ng = 0; ng < 8; ng++) {
            int gc = n0 + colw + ng * 8;
            size_t o1 = (size_t)(row0 + mt * 16) * DIM + gc;
            size_t o2 = o1 + 8 * DIM;
            if (SPLIT) {
                uint32_t h, l;
                split2(acc[mt][ng][0], acc[mt][ng][1], h, l);
                *(uint32_t*)(Ch + o1) = h; *(uint32_t*)(Cl + o1) = l;
                split2(acc[mt][ng][2], acc[mt][ng][3], h, l);
                *(uint32_t*)(Ch + o2) = h; *(uint32_t*)(Cl + o2) = l;
            } else {
                *(float2*)(C + o1) = make_float2(acc[mt][ng][0], acc[mt][ng][1]);
                *(float2*)(C + o2) = make_float2(acc[mt][ng][2], acc[mt][ng][3]);
            }
        }
    }
}

// ---------------------------------------------------------------------------
// HMMA flash-attention (R5-proven, byte-exact): 64 Q-rows/CTA, 8 warps,
// wm = wid&3 (16 Q-rows), wn = wid>>2 (128-key half), smem combine.
// ---------------------------------------------------------------------------
#define AP 144
#define OFF_QH 0
#define OFF_QL 9216
#define OFF_KH 18432
#define OFF_KL 55296
#define OFF_VH 92160
#define OFF_VL 129024
#define OFF_RED 165888
#define OFF_OC 166912
#define OFF_MS 184320
#define ATTN_SMEM 185344

__global__ void __launch_bounds__(256, 1)
attn_hmma_kernel(const __nv_bfloat16* __restrict__ Qh, const __nv_bfloat16* __restrict__ Ql,
                 const __nv_bfloat16* __restrict__ Kh, const __nv_bfloat16* __restrict__ Kl,
                 const __nv_bfloat16* __restrict__ Vh, const __nv_bfloat16* __restrict__ Vl,
                 const int* __restrict__ maskp,
                 __nv_bfloat16* __restrict__ Oh, __nv_bfloat16* __restrict__ Ol)
{
    extern __shared__ __align__(128) char smc[];
    const uint32_t sb = smem_u32(smc);
    float* redbuf = (float*)(smc + OFF_RED);
    float* Ocomb  = (float*)(smc + OFF_OC);
    int*   Msm    = (int*)(smc + OFF_MS);

    const int t = threadIdx.x, wid = t >> 5, lane = t & 31;
    const int b = blockIdx.y >> 4, h = blockIdx.y & 15;
    const int n0 = blockIdx.x * 64;

    #pragma unroll
    for (int i = 0; i < 2; i++) {
        int idx = t + i * 256;
        int r = idx >> 3, ch = idx & 7;
        uint32_t doff = (uint32_t)(r * AP + ch * 16);
        size_t src = (size_t)(b * SEQ_N + n0 + r) * DIM + h * HD + ch * 8;
        CP_ASYNC16(sb + OFF_QH + doff, Qh + src);
        CP_ASYNC16(sb + OFF_QL + doff, Ql + src);
    }
    #pragma unroll
    for (int i = 0; i < 8; i++) {
        int idx = t + i * 256;
        int r = idx >> 3, ch = idx & 7;
        uint32_t doff = (uint32_t)(r * AP + ch * 16);
        size_t src = (size_t)(b * SEQ_M + r) * DIM + h * HD + ch * 8;
        CP_ASYNC16(sb + OFF_KH + doff, Kh + src);
        CP_ASYNC16(sb + OFF_KL + doff, Kl + src);
        CP_ASYNC16(sb + OFF_VH + doff, Vh + src);
        CP_ASYNC16(sb + OFF_VL + doff, Vl + src);
    }
    CP_COMMIT();
    Msm[t] = maskp[b * SEQ_M + t];
    CP_WAIT(0);
    __syncthreads();

    const int wm = wid & 3, wn = wid >> 2;
    const int g = lane >> 3, lrw = lane & 7;
    const uint32_t a_off = (uint32_t)(((g & 1) * 8 + lrw) * AP + (g >> 1) * 16);
    const uint32_t b_off = (uint32_t)(((g >> 1) * 8 + lrw) * AP + (g & 1) * 16);

    float acc[16][4];
    #pragma unroll
    for (int j = 0; j < 16; j++)
        #pragma unroll
        for (int q = 0; q < 4; q++) acc[j][q] = 0.0f;

    #pragma unroll
    for (int ks = 0; ks < 4; ks++) {
        const uint32_t kb = (uint32_t)(ks * 32);
        uint32_t fAh[4], fAl[4];
        uint32_t aH = sb + OFF_QH + (uint32_t)(wm * 16) * AP + kb + a_off;
        uint32_t aL = sb + OFF_QL + (uint32_t)(wm * 16) * AP + kb + a_off;
        LDM_X4(fAh[0], fAh[1], fAh[2], fAh[3], aH);
        LDM_X4(fAl[0], fAl[1], fAl[2], fAl[3], aL);
        #pragma unroll
        for (int nt = 0; nt < 8; nt++) {
            uint32_t kH = sb + OFF_KH + (uint32_t)((wn * 128 + nt * 16)) * AP + kb + b_off;
            uint32_t kL = sb + OFF_KL + (uint32_t)((wn * 128 + nt * 16)) * AP + kb + b_off;
            uint32_t h0, h1, h2, h3, l0, l1, l2, l3;
            LDM_X4(h0, h1, h2, h3, kH);
            LDM_X4(l0, l1, l2, l3, kL);
            uint32_t bh0[2] = {h0, h1}, bh1[2] = {h2, h3};
            uint32_t bl0[2] = {l0, l1}, bl1[2] = {l2, l3};
            MMA_BF16(acc[nt * 2],     fAh, bh0);
            MMA_BF16(acc[nt * 2],     fAh, bl0);
            MMA_BF16(acc[nt * 2],     fAl, bh0);
            MMA_BF16(acc[nt * 2 + 1], fAh, bh1);
            MMA_BF16(acc[nt * 2 + 1], fAh, bl1);
            MMA_BF16(acc[nt * 2 + 1], fAl, bh1);
        }
    }

    const float scale = 0.125f;
    float m1 = -INFINITY, m2 = -INFINITY;
    #pragma unroll
    for (int j = 0; j < 16; j++) {
        int cb = wn * 128 + j * 8 + (lane & 3) * 2;
        bool k0 = Msm[cb] != 0, k1 = Msm[cb + 1] != 0;
        acc[j][0] = k0 ? acc[j][0] * scale : -1e30f;
        acc[j][1] = k1 ? acc[j][1] * scale : -1e30f;
        acc[j][2] = k0 ? acc[j][2] * scale : -1e30f;
        acc[j][3] = k1 ? acc[j][3] * scale : -1e30f;
        m1 = fmaxf(m1, fmaxf(acc[j][0], acc[j][1]));
        m2 = fmaxf(m2, fmaxf(acc[j][2], acc[j][3]));
    }
    m1 = fmaxf(m1, __shfl_xor_sync(0xffffffffu, m1, 1));
    m1 = fmaxf(m1, __shfl_xor_sync(0xffffffffu, m1, 2));
    m2 = fmaxf(m2, __shfl_xor_sync(0xffffffffu, m2, 1));
    m2 = fmaxf(m2, __shfl_xor_sync(0xffffffffu, m2, 2));

    const int r1 = wm * 16 + (lane >> 2), r2 = r1 + 8;
    if ((lane & 3) == 0) {
        redbuf[wn * 64 + r1] = m1;
        redbuf[wn * 64 + r2] = m2;
    }
    __syncthreads();
    const float M1 = fmaxf(m1, redbuf[(1 - wn) * 64 + r1]);
    const float M2 = fmaxf(m2, redbuf[(1 - wn) * 64 + r2]);

    float s1 = 0.0f, s2 = 0.0f;
    #pragma unroll
    for (int j = 0; j < 16; j++) {
        acc[j][0] = __expf(acc[j][0] - M1);
        acc[j][1] = __expf(acc[j][1] - M1);
        acc[j][2] = __expf(acc[j][2] - M2);
        acc[j][3] = __expf(acc[j][3] - M2);
        s1 += acc[j][0] + acc[j][1];
        s2 += acc[j][2] + acc[j][3];
    }
    s1 += __shfl_xor_sync(0xffffffffu, s1, 1);
    s1 += __shfl_xor_sync(0xffffffffu, s1, 2);
    s2 += __shfl_xor_sync(0xffffffffu, s2, 1);
    s2 += __shfl_xor_sync(0xffffffffu, s2, 2);
    float* sumbuf = redbuf + 128;
    if ((lane & 3) == 0) {
        sumbuf[wn * 64 + r1] = s1;
        sumbuf[wn * 64 + r2] = s2;
    }
    __syncthreads();
    const float inv1 = 1.0f / (s1 + sumbuf[(1 - wn) * 64 + r1]);
    const float inv2 = 1.0f / (s2 + sumbuf[(1 - wn) * 64 + r2]);

    float o[8][4];
    #pragma unroll
    for (int j = 0; j < 8; j++)
        #pragma unroll
        for (int q = 0; q < 4; q++) o[j][q] = 0.0f;

    #pragma unroll
    for (int kk = 0; kk < 8; kk++) {
        const int j0 = kk * 2, j1 = j0 + 1;
        uint32_t ph[4], pl[4];
        split2(acc[j0][0] * inv1, acc[j0][1] * inv1, ph[0], pl[0]);
        split2(acc[j0][2] * inv2, acc[j0][3] * inv2, ph[1], pl[1]);
        split2(acc[j1][0] * inv1, acc[j1][1] * inv1, ph[2], pl[2]);
        split2(acc[j1][2] * inv2, acc[j1][3] * inv2, ph[3], pl[3]);

        const uint32_t vrow = (uint32_t)(wn * 128 + kk * 16 + (g & 1) * 8 + lrw) * AP;
        #pragma unroll
        for (int ngp = 0; ngp < 4; ngp++) {
            const uint32_t vcol = (uint32_t)(((g >> 1) * 8 + ngp * 16) * 2);
            uint32_t h0, h1, h2, h3, l0, l1, l2, l3;
            LDM_X4T(h0, h1, h2, h3, sb + OFF_VH + vrow + vcol);
            LDM_X4T(l0, l1, l2, l3, sb + OFF_VL + vrow + vcol);
            uint32_t vh0[2] = {h0, h1}, vh1[2] = {h2, h3};
            uint32_t vl0[2] = {l0, l1}, vl1[2] = {l2, l3};
            MMA_BF16(o[ngp * 2],     ph, vh0);
            MMA_BF16(o[ngp * 2],     ph, vl0);
            MMA_BF16(o[ngp * 2],     pl, vh0);
            MMA_BF16(o[ngp * 2 + 1], ph, vh1);
            MMA_BF16(o[ngp * 2 + 1], ph, vl1);
            MMA_BF16(o[ngp * 2 + 1], pl, vh1);
        }
    }

    if (wn == 1) {
        #pragma unroll
        for (int j = 0; j < 8; j++) {
            int col = j * 8 + (lane & 3) * 2;
            *(float2*)&Ocomb[r1 * 68 + col] = make_float2(o[j][0], o[j][1]);
            *(float2*)&Ocomb[r2 * 68 + col] = make_float2(o[j][2], o[j][3]);
        }
    }
    __syncthreads();
    if (wn == 0) {
        #pragma unroll
        for (int j = 0; j < 8; j++) {
            int col = j * 8 + (lane & 3) * 2;
            float2 p1 = *(float2*)&Ocomb[r1 * 68 + col];
            float2 p2 = *(float2*)&Ocomb[r2 * 68 + col];
            uint32_t hh, ll;
            size_t go1 = (size_t)(b * SEQ_N + n0 + r1) * DIM + h * HD + col;
            size_t go2 = (size_t)(b * SEQ_N + n0 + r2) * DIM + h * HD + col;
            split2(o[j][0] + p1.x, o[j][1] + p1.y, hh, ll);
            *(uint32_t*)(Oh + go1) = hh; *(uint32_t*)(Ol + go1) = ll;
            split2(o[j][2] + p2.x, o[j][3] + p2.y, hh, ll);
            *(uint32_t*)(Oh + go2) = hh; *(uint32_t*)(Ol + go2) = ll;
        }
    }
}

// ---------------------------------------------------------------------------
// Host launcher (R5 plumbing: separate K and V projections)
// ---------------------------------------------------------------------------
extern "C" void kernel_launch(void* const* d_in, const int* in_sizes, int n_in,
                              void* d_out, int out_size)
{
    const float* x    = (const float*)d_in[0];
    const float* ctx  = (const float*)d_in[1];
    const int*   mask = (const int*)d_in[2];
    const float* Wq   = (const float*)d_in[3];
    const float* Wk   = (const float*)d_in[4];
    const float* Wv   = (const float*)d_in[5];
    const float* Wo   = (const float*)d_in[6];
    float*       out  = (float*)d_out;

    __nv_bfloat16 *Ahp, *Alp, *Chp, *Clp, *Bhp, *Blp, *Qhp, *Qlp, *Khp, *Klp, *Vhp, *Vlp;
    cudaGetSymbolAddress((void**)&Ahp, g_Ah);
    cudaGetSymbolAddress((void**)&Alp, g_Al);
    cudaGetSymbolAddress((void**)&Chp, g_Ch);
    cudaGetSymbolAddress((void**)&Clp, g_Cl);
    cudaGetSymbolAddress((void**)&Bhp, g_Bh);
    cudaGetSymbolAddress((void**)&Blp, g_Bl);
    cudaGetSymbolAddress((void**)&Qhp, g_Qh);
    cudaGetSymbolAddress((void**)&Qlp, g_Ql);
    cudaGetSymbolAddress((void**)&Khp, g_Kh);
    cudaGetSymbolAddress((void**)&Klp, g_Kl);
    cudaGetSymbolAddress((void**)&Vhp, g_Vh);
    cudaGetSymbolAddress((void**)&Vlp, g_Vl);

    cudaFuncSetAttribute(gemm_hmma_kernel<0>, cudaFuncAttributeMaxDynamicSharedMemorySize, GEMM_SMEM);
    cudaFuncSetAttribute(gemm_hmma_kernel<1>, cudaFuncAttributeMaxDynamicSharedMemorySize, GEMM_SMEM);
    cudaFuncSetAttribute(attn_hmma_kernel, cudaFuncAttributeMaxDynamicSharedMemorySize, ATTN_SMEM);

    const int n4x = ROWS_X * DIM / 4;
    const int n4c = ROWS_C * CTX_DIM / 4;
    dim3 tb32(32, 8);

    // Q projection -> split bf16
    split_kernel<<<n4x / 256, 256>>>(x, Ahp, Alp, n4x);
    transpose_split_kernel<<<dim3(DIM / 32, DIM / 32), tb32>>>(Wq, Bhp, Blp, DIM, DIM);
    gemm_hmma_kernel<1><<<dim3(DIM / BN, ROWS_X / BM), 256, GEMM_SMEM>>>(
        Ahp, Alp, Bhp, Blp, nullptr, Qhp, Qlp, DIM);

    // K projection -> split bf16
    split_kernel<<<n4c / 256, 256>>>(ctx, Chp, Clp, n4c);
    transpose_split_kernel<<<dim3(DIM / 32, CTX_DIM / 32), tb32>>>(Wk, Bhp, Blp, CTX_DIM, DIM);
    gemm_hmma_kernel<1><<<dim3(DIM / BN, ROWS_C / BM), 256, GEMM_SMEM>>>(
        Chp, Clp, Bhp, Blp, nullptr, Khp, Klp, CTX_DIM);

    // V projection -> split bf16
    transpose_split_kernel<<<dim3(DIM / 32, CTX_DIM / 32), tb32>>>(Wv, Bhp, Blp, CTX_DIM, DIM);
    gemm_hmma_kernel<1><<<dim3(DIM / BN, ROWS_C / BM), 256, GEMM_SMEM>>>(
        Chp, Clp, Bhp, Blp, nullptr, Vhp, Vlp, CTX_DIM);

    // Flash attention -> split bf16 into g_Ah/g_Al
    attn_hmma_kernel<<<dim3(SEQ_N / 64, BATCH * HEADS), 256, ATTN_SMEM>>>(
        Qhp, Qlp, Khp, Klp, Vhp, Vlp, mask, Ahp, Alp);

    // O projection -> fp32 final output
    transpose_split_kernel<<<dim3(DIM / 32, DIM / 32), tb32>>>(Wo, Bhp, Blp, DIM, DIM);
    gemm_hmma_kernel<0><<<dim3(DIM / BN, ROWS_X / BM), 256, GEMM_SMEM>>>(
        Ahp, Alp, Bhp, Blp, out, nullptr, nullptr, DIM);
}

// round 9
// speedup vs baseline: 1.1451x; 1.1451x over previous
#include <cuda_runtime.h>
#include <cuda_bf16.h>
#include <math.h>
#include <stdint.h>

// Problem constants
#define BATCH 4
#define SEQ_N 4096
#define SEQ_M 256
#define DIM 1024
#define CTX_DIM 768
#define HEADS 16
#define HD 64
#define ROWS_X (BATCH * SEQ_N)      // 16384
#define ROWS_C (BATCH * SEQ_M)      // 1024

// Scratch (device globals)
__device__ __nv_bfloat16 g_Ah[ROWS_X * DIM];
__device__ __nv_bfloat16 g_Al[ROWS_X * DIM];
__device__ __nv_bfloat16 g_Ch[ROWS_C * CTX_DIM];
__device__ __nv_bfloat16 g_Cl[ROWS_C * CTX_DIM];
__device__ __nv_bfloat16 g_Bh[DIM * DIM];
__device__ __nv_bfloat16 g_Bl[DIM * DIM];
__device__ __nv_bfloat16 g_Qh[ROWS_X * DIM];
__device__ __nv_bfloat16 g_Ql[ROWS_X * DIM];
__device__ __nv_bfloat16 g_Kh[ROWS_C * DIM];
__device__ __nv_bfloat16 g_Kl[ROWS_C * DIM];
__device__ __nv_bfloat16 g_Vh[ROWS_C * DIM];
__device__ __nv_bfloat16 g_Vl[ROWS_C * DIM];

// ---------------------------------------------------------------------------
// PTX helpers (sm_80+ portable)
// ---------------------------------------------------------------------------
__device__ __forceinline__ uint32_t smem_u32(const void* p) {
    uint32_t a;
    asm("{ .reg .u64 t; cvta.to.shared.u64 t, %1; cvt.u32.u64 %0, t; }" : "=r"(a) : "l"(p));
    return a;
}
#define CP_ASYNC16(dst, src) \
    asm volatile("cp.async.cg.shared.global [%0], [%1], 16;" :: "r"(dst), "l"(src))
#define CP_COMMIT() asm volatile("cp.async.commit_group;" ::: "memory")
#define CP_WAIT(n)  asm volatile("cp.async.wait_group %0;" :: "n"(n) : "memory")

#define LDM_X4(r0, r1, r2, r3, a) \
    asm volatile("ldmatrix.sync.aligned.m8n8.x4.shared.b16 {%0,%1,%2,%3}, [%4];" \
                 : "=r"(r0), "=r"(r1), "=r"(r2), "=r"(r3) : "r"(a))
#define LDM_X4T(r0, r1, r2, r3, a) \
    asm volatile("ldmatrix.sync.aligned.m8n8.x4.trans.shared.b16 {%0,%1,%2,%3}, [%4];" \
                 : "=r"(r0), "=r"(r1), "=r"(r2), "=r"(r3) : "r"(a))

#define MMA_BF16(d, a, b) \
    asm volatile("mma.sync.aligned.m16n8k16.row.col.f32.bf16.bf16.f32 " \
                 "{%0,%1,%2,%3},{%4,%5,%6,%7},{%8,%9},{%0,%1,%2,%3};" \
                 : "+f"((d)[0]), "+f"((d)[1]), "+f"((d)[2]), "+f"((d)[3]) \
                 : "r"((a)[0]), "r"((a)[1]), "r"((a)[2]), "r"((a)[3]), \
                   "r"((b)[0]), "r"((b)[1]))

__device__ __forceinline__ void split2(float x, float y, uint32_t& h, uint32_t& l) {
    __nv_bfloat162 hb = __float22bfloat162_rn(make_float2(x, y));
    float2 hf = __bfloat1622float2(hb);
    __nv_bfloat162 lb = __float22bfloat162_rn(make_float2(x - hf.x, y - hf.y));
    h = *(uint32_t*)&hb;
    l = *(uint32_t*)&lb;
}

// ---------------------------------------------------------------------------
// fp32 -> bf16 hi/lo split
// ---------------------------------------------------------------------------
__global__ void split_kernel(const float* __restrict__ X, __nv_bfloat16* __restrict__ Xh,
                             __nv_bfloat16* __restrict__ Xl, int n4)
{
    int i = blockIdx.x * blockDim.x + threadIdx.x;
    if (i >= n4) return;
    float4 v = ((const float4*)X)[i];
    float a[4] = {v.x, v.y, v.z, v.w};
    __nv_bfloat16 h[4], l[4];
    #pragma unroll
    for (int j = 0; j < 4; j++) {
        h[j] = __float2bfloat16(a[j]);
        l[j] = __float2bfloat16(a[j] - __bfloat162float(h[j]));
    }
    __nv_bfloat162* Hp = (__nv_bfloat162*)(Xh + 4 * (size_t)i);
    __nv_bfloat162* Lp = (__nv_bfloat162*)(Xl + 4 * (size_t)i);
    Hp[0] = __nv_bfloat162(h[0], h[1]); Hp[1] = __nv_bfloat162(h[2], h[3]);
    Lp[0] = __nv_bfloat162(l[0], l[1]); Lp[1] = __nv_bfloat162(l[2], l[3]);
}

// ---------------------------------------------------------------------------
// W[K][N] -> Th/Tl[N][K] bf16 hi/lo (transpose + split)
// ---------------------------------------------------------------------------
__global__ void transpose_split_kernel(const float* __restrict__ W, __nv_bfloat16* __restrict__ Th,
                                       __nv_bfloat16* __restrict__ Tl, int K, int N)
{
    __shared__ float tile[32][33];
    int n0 = blockIdx.x * 32, k0 = blockIdx.y * 32;
    int tx = threadIdx.x, ty = threadIdx.y;
    #pragma unroll
    for (int j = ty; j < 32; j += 8)
        tile[j][tx] = W[(size_t)(k0 + j) * N + n0 + tx];
    __syncthreads();
    #pragma unroll
    for (int j = ty; j < 32; j += 8) {
        float v = tile[tx][j];
        __nv_bfloat16 h = __float2bfloat16(v);
        __nv_bfloat16 l = __float2bfloat16(v - __bfloat162float(h));
        size_t o = (size_t)(n0 + j) * K + k0 + tx;
        Th[o] = h; Tl[o] = l;
    }
}

// ---------------------------------------------------------------------------
// HMMA bf16-split GEMM (R5-proven): 128x128x32 CTA tile, 8 warps of 64x32,
// 2-stage cp.async double buffer. SPLIT=0: fp32 out. SPLIT=1: bf16 hi/lo out.
// ---------------------------------------------------------------------------
#define BM 128
#define BN 128
#define BK 32
#define PITCH 80
#define TILE_B (128 * PITCH)        // 10240
#define STAGE  (4 * TILE_B)         // 40960
#define GEMM_SMEM (2 * STAGE)       // 81920

template<int SPLIT>
__global__ void __launch_bounds__(256, 1)
gemm_hmma_kernel(const __nv_bfloat16* __restrict__ Ah, const __nv_bfloat16* __restrict__ Al,
                 const __nv_bfloat16* __restrict__ Bh, const __nv_bfloat16* __restrict__ Bl,
                 float* __restrict__ C, __nv_bfloat16* __restrict__ Ch,
                 __nv_bfloat16* __restrict__ Cl, int M, int K)
{
    extern __shared__ __align__(128) char sm[];
    const uint32_t sb = smem_u32(sm);
    const int t = threadIdx.x, wid = t >> 5, lane = t & 31;
    const int m0 = blockIdx.y * BM, n0 = blockIdx.x * BN;
    const int NC = K / BK;
    const int wr = wid & 1, wc = wid >> 1;

    const int lr0 = t >> 2;
    const int lch = t & 3;

    const int g = lane >> 3, lrw = lane & 7;
    const uint32_t a_off = (uint32_t)(((g & 1) * 8 + lrw) * PITCH + (g >> 1) * 16);
    const uint32_t b_off = (uint32_t)(((g >> 1) * 8 + lrw) * PITCH + (g & 1) * 16);

    float acc[4][4][4];
    #pragma unroll
    for (int mt = 0; mt < 4; mt++)
        #pragma unroll
        for (int ng = 0; ng < 4; ng++)
            #pragma unroll
            for (int q = 0; q < 4; q++) acc[mt][ng][q] = 0.0f;

    auto issue = [&](int c) {
        const int buf = c & 1;
        const uint32_t stg = sb + buf * STAGE;
        const int kt = c * BK;
        #pragma unroll
        for (int i = 0; i < 2; i++) {
            const int r = lr0 + i * 64;
            const uint32_t doff = (uint32_t)(r * PITCH + lch * 16);
            const size_t sa = (size_t)(m0 + r) * K + kt + lch * 8;
            const size_t sbi = (size_t)(n0 + r) * K + kt + lch * 8;
            CP_ASYNC16(stg + doff,               Ah + sa);
            CP_ASYNC16(stg + TILE_B + doff,      Al + sa);
            CP_ASYNC16(stg + 2 * TILE_B + doff,  Bh + sbi);
            CP_ASYNC16(stg + 3 * TILE_B + doff,  Bl + sbi);
        }
        CP_COMMIT();
    };

    issue(0);

    for (int c = 0; c < NC; c++) {
        if (c + 1 < NC) { issue(c + 1); CP_WAIT(1); }
        else            { CP_WAIT(0); }
        __syncthreads();

        const uint32_t stg = sb + (c & 1) * STAGE;
        const uint32_t aH = stg + (uint32_t)(wr * 64) * PITCH;
        const uint32_t aL = aH + TILE_B;
        const uint32_t bH = stg + 2 * TILE_B + (uint32_t)(wc * 32) * PITCH;
        const uint32_t bL = bH + TILE_B;

        #pragma unroll
        for (int ks = 0; ks < 2; ks++) {
            const uint32_t kb = (uint32_t)(ks * 32);
            uint32_t fAh[4][4], fAl[4][4], fBh[4][2], fBl[4][2];
            #pragma unroll
            for (int mt = 0; mt < 4; mt++) {
                uint32_t ad = aH + (uint32_t)(mt * 16) * PITCH + kb + a_off;
                LDM_X4(fAh[mt][0], fAh[mt][1], fAh[mt][2], fAh[mt][3], ad);
                uint32_t ad2 = aL + (uint32_t)(mt * 16) * PITCH + kb + a_off;
                LDM_X4(fAl[mt][0], fAl[mt][1], fAl[mt][2], fAl[mt][3], ad2);
            }
            #pragma unroll
            for (int nt = 0; nt < 2; nt++) {
                uint32_t bd = bH + (uint32_t)(nt * 16) * PITCH + kb + b_off;
                uint32_t r0, r1, r2, r3;
                LDM_X4(r0, r1, r2, r3, bd);
                fBh[nt * 2][0] = r0; fBh[nt * 2][1] = r1;
                fBh[nt * 2 + 1][0] = r2; fBh[nt * 2 + 1][1] = r3;
                uint32_t bd2 = bL + (uint32_t)(nt * 16) * PITCH + kb + b_off;
                LDM_X4(r0, r1, r2, r3, bd2);
                fBl[nt * 2][0] = r0; fBl[nt * 2][1] = r1;
                fBl[nt * 2 + 1][0] = r2; fBl[nt * 2 + 1][1] = r3;
            }
            #pragma unroll
            for (int mt = 0; mt < 4; mt++) {
                #pragma unroll
                for (int ng = 0; ng < 4; ng++) {
                    MMA_BF16(acc[mt][ng], fAh[mt], fBh[ng]);
                    MMA_BF16(acc[mt][ng], fAh[mt], fBl[ng]);
                    MMA_BF16(acc[mt][ng], fAl[mt], fBh[ng]);
                }
            }
        }
        __syncthreads();
    }

    const int row0 = m0 + wr * 64 + lane / 4;
    const int col0 = n0 + wc * 32 + (lane % 4) * 2;
    #pragma unroll
    for (int mt = 0; mt < 4; mt++) {
        #pragma unroll
        for (int ng = 0; ng < 4; ng++) {
            size_t o1 = (size_t)(row0 + mt * 16) * DIM + col0 + ng * 8;
            size_t o2 = o1 + 8 * DIM;
            if (SPLIT) {
                uint32_t h, l;
                split2(acc[mt][ng][0], acc[mt][ng][1], h, l);
                *(uint32_t*)(Ch + o1) = h; *(uint32_t*)(Cl + o1) = l;
                split2(acc[mt][ng][2], acc[mt][ng][3], h, l);
                *(uint32_t*)(Ch + o2) = h; *(uint32_t*)(Cl + o2) = l;
            } else {
                *(float2*)(C + o1) = make_float2(acc[mt][ng][0], acc[mt][ng][1]);
                *(float2*)(C + o2) = make_float2(acc[mt][ng][2], acc[mt][ng][3]);
            }
        }
    }
}

// ---------------------------------------------------------------------------
// HMMA flash-attention: 128 Q-rows/CTA, 8 warps each owning 16 rows x all keys.
// Two 128-key halves, online softmax. FIX vs R6/R7: the per-half row sums
// s1/s2 are shuffle-reduced across the 4 lanes sharing a row before being
// accumulated into S1/S2 (previously the normalizer was a partial sum).
// ---------------------------------------------------------------------------
#define AP 144
#define OFF_QH 0
#define OFF_QL 18432
#define OFF_KH 36864
#define OFF_KL 73728
#define OFF_VH 110592
#define OFF_VL 147456
#define OFF_MS 184320
#define ATTN_SMEM 185344

__global__ void __launch_bounds__(256, 1)
attn_hmma_kernel(const __nv_bfloat16* __restrict__ Qh, const __nv_bfloat16* __restrict__ Ql,
                 const __nv_bfloat16* __restrict__ Kh, const __nv_bfloat16* __restrict__ Kl,
                 const __nv_bfloat16* __restrict__ Vh, const __nv_bfloat16* __restrict__ Vl,
                 const int* __restrict__ maskp,
                 __nv_bfloat16* __restrict__ Oh, __nv_bfloat16* __restrict__ Ol)
{
    extern __shared__ __align__(128) char smc[];
    const uint32_t sb = smem_u32(smc);
    int* Msm = (int*)(smc + OFF_MS);

    const int t = threadIdx.x, wid = t >> 5, lane = t & 31;
    const int b = blockIdx.y >> 4, h = blockIdx.y & 15;
    const int n0 = blockIdx.x * 128;

    #pragma unroll
    for (int i = 0; i < 4; i++) {
        int idx = t + i * 256;              // < 1024 : Q 128 rows x 8 chunks
        int r = idx >> 3, ch = idx & 7;
        uint32_t doff = (uint32_t)(r * AP + ch * 16);
        size_t src = (size_t)(b * SEQ_N + n0 + r) * DIM + h * HD + ch * 8;
        CP_ASYNC16(sb + OFF_QH + doff, Qh + src);
        CP_ASYNC16(sb + OFF_QL + doff, Ql + src);
    }
    #pragma unroll
    for (int i = 0; i < 8; i++) {
        int idx = t + i * 256;              // < 2048 : K/V 256 rows x 8 chunks
        int r = idx >> 3, ch = idx & 7;
        uint32_t doff = (uint32_t)(r * AP + ch * 16);
        size_t src = (size_t)(b * SEQ_M + r) * DIM + h * HD + ch * 8;
        CP_ASYNC16(sb + OFF_KH + doff, Kh + src);
        CP_ASYNC16(sb + OFF_KL + doff, Kl + src);
        CP_ASYNC16(sb + OFF_VH + doff, Vh + src);
        CP_ASYNC16(sb + OFF_VL + doff, Vl + src);
    }
    CP_COMMIT();
    Msm[t] = maskp[b * SEQ_M + t];
    CP_WAIT(0);
    __syncthreads();

    const int wm = wid;                      // 0..7: rows wm*16..+15
    const int g = lane >> 3, lrw = lane & 7;
    const uint32_t a_off = (uint32_t)(((g & 1) * 8 + lrw) * AP + (g >> 1) * 16);
    const uint32_t b_off = (uint32_t)(((g >> 1) * 8 + lrw) * AP + (g & 1) * 16);

    float o[8][4];
    #pragma unroll
    for (int j = 0; j < 8; j++)
        #pragma unroll
        for (int q = 0; q < 4; q++) o[j][q] = 0.0f;
    float M1 = -INFINITY, M2 = -INFINITY, S1 = 0.0f, S2 = 0.0f;

    const float scale = 0.125f;

    #pragma unroll
    for (int hf = 0; hf < 2; hf++) {
        float acc[16][4];
        #pragma unroll
        for (int j = 0; j < 16; j++)
            #pragma unroll
            for (int q = 0; q < 4; q++) acc[j][q] = 0.0f;

        #pragma unroll
        for (int ks = 0; ks < 4; ks++) {
            const uint32_t kb = (uint32_t)(ks * 32);
            uint32_t fAh[4], fAl[4];
            LDM_X4(fAh[0], fAh[1], fAh[2], fAh[3],
                   sb + OFF_QH + (uint32_t)(wm * 16) * AP + kb + a_off);
            LDM_X4(fAl[0], fAl[1], fAl[2], fAl[3],
                   sb + OFF_QL + (uint32_t)(wm * 16) * AP + kb + a_off);
            #pragma unroll
            for (int nt = 0; nt < 8; nt++) {
                uint32_t krow = (uint32_t)(hf * 128 + nt * 16) * AP + kb + b_off;
                uint32_t h0, h1, h2, h3, l0, l1, l2, l3;
                LDM_X4(h0, h1, h2, h3, sb + OFF_KH + krow);
                LDM_X4(l0, l1, l2, l3, sb + OFF_KL + krow);
                uint32_t bh0[2] = {h0, h1}, bh1[2] = {h2, h3};
                uint32_t bl0[2] = {l0, l1}, bl1[2] = {l2, l3};
                MMA_BF16(acc[nt * 2],     fAh, bh0);
                MMA_BF16(acc[nt * 2],     fAh, bl0);
                MMA_BF16(acc[nt * 2],     fAl, bh0);
                MMA_BF16(acc[nt * 2 + 1], fAh, bh1);
                MMA_BF16(acc[nt * 2 + 1], fAh, bl1);
                MMA_BF16(acc[nt * 2 + 1], fAl, bh1);
            }
        }

        float m1 = -INFINITY, m2 = -INFINITY;
        #pragma unroll
        for (int j = 0; j < 16; j++) {
            int cb = hf * 128 + j * 8 + (lane & 3) * 2;
            bool k0 = Msm[cb] != 0, k1 = Msm[cb + 1] != 0;
            acc[j][0] = k0 ? acc[j][0] * scale : -1e30f;
            acc[j][1] = k1 ? acc[j][1] * scale : -1e30f;
            acc[j][2] = k0 ? acc[j][2] * scale : -1e30f;
            acc[j][3] = k1 ? acc[j][3] * scale : -1e30f;
            m1 = fmaxf(m1, fmaxf(acc[j][0], acc[j][1]));
            m2 = fmaxf(m2, fmaxf(acc[j][2], acc[j][3]));
        }
        m1 = fmaxf(m1, __shfl_xor_sync(0xffffffffu, m1, 1));
        m1 = fmaxf(m1, __shfl_xor_sync(0xffffffffu, m1, 2));
        m2 = fmaxf(m2, __shfl_xor_sync(0xffffffffu, m2, 1));
        m2 = fmaxf(m2, __shfl_xor_sync(0xffffffffu, m2, 2));

        float M1n = fmaxf(M1, m1), M2n = fmaxf(M2, m2);
        float sc1 = __expf(M1 - M1n), sc2 = __expf(M2 - M2n);
        #pragma unroll
        for (int j = 0; j < 8; j++) {
            o[j][0] *= sc1; o[j][1] *= sc1;
            o[j][2] *= sc2; o[j][3] *= sc2;
        }
        S1 *= sc1; S2 *= sc2;
        M1 = M1n; M2 = M2n;

        float s1 = 0.0f, s2 = 0.0f;
        #pragma unroll
        for (int j = 0; j < 16; j++) {
            acc[j][0] = __expf(acc[j][0] - M1);
            acc[j][1] = __expf(acc[j][1] - M1);
            acc[j][2] = __expf(acc[j][2] - M2);
            acc[j][3] = __expf(acc[j][3] - M2);
            s1 += acc[j][0] + acc[j][1];
            s2 += acc[j][2] + acc[j][3];
        }
        // FIX: reduce the row sum across the 4 lanes sharing each row
        s1 += __shfl_xor_sync(0xffffffffu, s1, 1);
        s1 += __shfl_xor_sync(0xffffffffu, s1, 2);
        s2 += __shfl_xor_sync(0xffffffffu, s2, 1);
        s2 += __shfl_xor_sync(0xffffffffu, s2, 2);
        S1 += s1; S2 += s2;

        #pragma unroll
        for (int kk = 0; kk < 8; kk++) {
            const int j0 = kk * 2, j1 = j0 + 1;
            uint32_t ph[4], pl[4];
            split2(acc[j0][0], acc[j0][1], ph[0], pl[0]);
            split2(acc[j0][2], acc[j0][3], ph[1], pl[1]);
            split2(acc[j1][0], acc[j1][1], ph[2], pl[2]);
            split2(acc[j1][2], acc[j1][3], ph[3], pl[3]);

            const uint32_t vrow = (uint32_t)(hf * 128 + kk * 16 + (g & 1) * 8 + lrw) * AP;
            #pragma unroll
            for (int ngp = 0; ngp < 4; ngp++) {
                const uint32_t vcol = (uint32_t)(((g >> 1) * 8 + ngp * 16) * 2);
                uint32_t h0, h1, h2, h3, l0, l1, l2, l3;
                LDM_X4T(h0, h1, h2, h3, sb + OFF_VH + vrow + vcol);
                LDM_X4T(l0, l1, l2, l3, sb + OFF_VL + vrow + vcol);
                uint32_t vh0[2] = {h0, h1}, vh1[2] = {h2, h3};
                uint32_t vl0[2] = {l0, l1}, vl1[2] = {l2, l3};
                MMA_BF16(o[ngp * 2],     ph, vh0);
                MMA_BF16(o[ngp * 2],     ph, vl0);
                MMA_BF16(o[ngp * 2],     pl, vh0);
                MMA_BF16(o[ngp * 2 + 1], ph, vh1);
                MMA_BF16(o[ngp * 2 + 1], ph, vl1);
                MMA_BF16(o[ngp * 2 + 1], pl, vh1);
            }
        }
    }

    const float inv1 = 1.0f / S1, inv2 = 1.0f / S2;
    const int r1 = wm * 16 + (lane >> 2), r2 = r1 + 8;
    #pragma unroll
    for (int j = 0; j < 8; j++) {
        int col = j * 8 + (lane & 3) * 2;
        size_t go1 = (size_t)(b * SEQ_N + n0 + r1) * DIM + h * HD + col;
        size_t go2 = (size_t)(b * SEQ_N + n0 + r2) * DIM + h * HD + col;
        uint32_t hh, ll;
        split2(o[j][0] * inv1, o[j][1] * inv1, hh, ll);
        *(uint32_t*)(Oh + go1) = hh; *(uint32_t*)(Ol + go1) = ll;
        split2(o[j][2] * inv2, o[j][3] * inv2, hh, ll);
        *(uint32_t*)(Oh + go2) = hh; *(uint32_t*)(Ol + go2) = ll;
    }
}

// ---------------------------------------------------------------------------
// Host launcher
// ---------------------------------------------------------------------------
extern "C" void kernel_launch(void* const* d_in, const int* in_sizes, int n_in,
                              void* d_out, int out_size)
{
    const float* x    = (const float*)d_in[0];
    const float* ctx  = (const float*)d_in[1];
    const int*   mask = (const int*)d_in[2];
    const float* Wq   = (const float*)d_in[3];
    const float* Wk   = (const float*)d_in[4];
    const float* Wv   = (const float*)d_in[5];
    const float* Wo   = (const float*)d_in[6];
    float*       out  = (float*)d_out;

    __nv_bfloat16 *Ahp, *Alp, *Chp, *Clp, *Bhp, *Blp, *Qhp, *Qlp, *Khp, *Klp, *Vhp, *Vlp;
    cudaGetSymbolAddress((void**)&Ahp, g_Ah);
    cudaGetSymbolAddress((void**)&Alp, g_Al);
    cudaGetSymbolAddress((void**)&Chp, g_Ch);
    cudaGetSymbolAddress((void**)&Clp, g_Cl);
    cudaGetSymbolAddress((void**)&Bhp, g_Bh);
    cudaGetSymbolAddress((void**)&Blp, g_Bl);
    cudaGetSymbolAddress((void**)&Qhp, g_Qh);
    cudaGetSymbolAddress((void**)&Qlp, g_Ql);
    cudaGetSymbolAddress((void**)&Khp, g_Kh);
    cudaGetSymbolAddress((void**)&Klp, g_Kl);
    cudaGetSymbolAddress((void**)&Vhp, g_Vh);
    cudaGetSymbolAddress((void**)&Vlp, g_Vl);

    cudaFuncSetAttribute(gemm_hmma_kernel<0>, cudaFuncAttributeMaxDynamicSharedMemorySize, GEMM_SMEM);
    cudaFuncSetAttribute(gemm_hmma_kernel<1>, cudaFuncAttributeMaxDynamicSharedMemorySize, GEMM_SMEM);
    cudaFuncSetAttribute(attn_hmma_kernel, cudaFuncAttributeMaxDynamicSharedMemorySize, ATTN_SMEM);

    const int n4x = ROWS_X * DIM / 4;
    const int n4c = ROWS_C * CTX_DIM / 4;
    dim3 tb32(32, 8);

    // Q projection -> split bf16
    split_kernel<<<n4x / 256, 256>>>(x, Ahp, Alp, n4x);
    transpose_split_kernel<<<dim3(DIM / 32, DIM / 32), tb32>>>(Wq, Bhp, Blp, DIM, DIM);
    gemm_hmma_kernel<1><<<dim3(DIM / BN, ROWS_X / BM), 256, GEMM_SMEM>>>(
        Ahp, Alp, Bhp, Blp, nullptr, Qhp, Qlp, ROWS_X, DIM);

    // K projection -> split bf16
    split_kernel<<<n4c / 256, 256>>>(ctx, Chp, Clp, n4c);
    transpose_split_kernel<<<dim3(DIM / 32, CTX_DIM / 32), tb32>>>(Wk, Bhp, Blp, CTX_DIM, DIM);
    gemm_hmma_kernel<1><<<dim3(DIM / BN, ROWS_C / BM), 256, GEMM_SMEM>>>(
        Chp, Clp, Bhp, Blp, nullptr, Khp, Klp, ROWS_C, CTX_DIM);

    // V projection -> split bf16
    transpose_split_kernel<<<dim3(DIM / 32, CTX_DIM / 32), tb32>>>(Wv, Bhp, Blp, CTX_DIM, DIM);
    gemm_hmma_kernel<1><<<dim3(DIM / BN, ROWS_C / BM), 256, GEMM_SMEM>>>(
        Chp, Clp, Bhp, Blp, nullptr, Vhp, Vlp, ROWS_C, CTX_DIM);

    // Flash attention -> split bf16 into g_Ah/g_Al
    attn_hmma_kernel<<<dim3(SEQ_N / 128, BATCH * HEADS), 256, ATTN_SMEM>>>(
        Qhp, Qlp, Khp, Klp, Vhp, Vlp, mask, Ahp, Alp);

    // O projection -> fp32 final output
    transpose_split_kernel<<<dim3(DIM / 32, DIM / 32), tb32>>>(Wo, Bhp, Blp, DIM, DIM);
    gemm_hmma_kernel<0><<<dim3(DIM / BN, ROWS_X / BM), 256, GEMM_SMEM>>>(
        Ahp, Alp, Bhp, Blp, out, nullptr, nullptr, ROWS_X, DIM);
}

// round 10
// speedup vs baseline: 1.2569x; 1.0976x over previous
#include <cuda_runtime.h>
#include <cuda_bf16.h>
#include <math.h>
#include <stdint.h>

// Problem constants
#define BATCH 4
#define SEQ_N 4096
#define SEQ_M 256
#define DIM 1024
#define CTX_DIM 768
#define HEADS 16
#define HD 64
#define ROWS_X (BATCH * SEQ_N)      // 16384
#define ROWS_C (BATCH * SEQ_M)      // 1024

// Scratch (device globals)
__device__ __nv_bfloat16 g_Ah[ROWS_X * DIM];
__device__ __nv_bfloat16 g_Al[ROWS_X * DIM];
__device__ __nv_bfloat16 g_Ch[ROWS_C * CTX_DIM];
__device__ __nv_bfloat16 g_Cl[ROWS_C * CTX_DIM];
__device__ __nv_bfloat16 g_Bh[2048 * 1024];
__device__ __nv_bfloat16 g_Bl[2048 * 1024];
__device__ __nv_bfloat16 g_Qh[ROWS_X * DIM];
__device__ __nv_bfloat16 g_Ql[ROWS_X * DIM];
__device__ __nv_bfloat16 g_Kh[ROWS_C * DIM];
__device__ __nv_bfloat16 g_Kl[ROWS_C * DIM];
__device__ __nv_bfloat16 g_Vh[ROWS_C * DIM];
__device__ __nv_bfloat16 g_Vl[ROWS_C * DIM];

// ---------------------------------------------------------------------------
// PTX helpers (sm_80+ portable)
// ---------------------------------------------------------------------------
__device__ __forceinline__ uint32_t smem_u32(const void* p) {
    uint32_t a;
    asm("{ .reg .u64 t; cvta.to.shared.u64 t, %1; cvt.u32.u64 %0, t; }" : "=r"(a) : "l"(p));
    return a;
}
#define CP_ASYNC16(dst, src) \
    asm volatile("cp.async.cg.shared.global [%0], [%1], 16;" :: "r"(dst), "l"(src))
#define CP_COMMIT() asm volatile("cp.async.commit_group;" ::: "memory")
#define CP_WAIT(n)  asm volatile("cp.async.wait_group %0;" :: "n"(n) : "memory")

#define LDM_X4(r0, r1, r2, r3, a) \
    asm volatile("ldmatrix.sync.aligned.m8n8.x4.shared.b16 {%0,%1,%2,%3}, [%4];" \
                 : "=r"(r0), "=r"(r1), "=r"(r2), "=r"(r3) : "r"(a))
#define LDM_X4T(r0, r1, r2, r3, a) \
    asm volatile("ldmatrix.sync.aligned.m8n8.x4.trans.shared.b16 {%0,%1,%2,%3}, [%4];" \
                 : "=r"(r0), "=r"(r1), "=r"(r2), "=r"(r3) : "r"(a))

#define MMA_BF16(d, a, b) \
    asm volatile("mma.sync.aligned.m16n8k16.row.col.f32.bf16.bf16.f32 " \
                 "{%0,%1,%2,%3},{%4,%5,%6,%7},{%8,%9},{%0,%1,%2,%3};" \
                 : "+f"((d)[0]), "+f"((d)[1]), "+f"((d)[2]), "+f"((d)[3]) \
                 : "r"((a)[0]), "r"((a)[1]), "r"((a)[2]), "r"((a)[3]), \
                   "r"((b)[0]), "r"((b)[1]))

__device__ __forceinline__ void split2(float x, float y, uint32_t& h, uint32_t& l) {
    __nv_bfloat162 hb = __float22bfloat162_rn(make_float2(x, y));
    float2 hf = __bfloat1622float2(hb);
    __nv_bfloat162 lb = __float22bfloat162_rn(make_float2(x - hf.x, y - hf.y));
    h = *(uint32_t*)&hb;
    l = *(uint32_t*)&lb;
}

// ---------------------------------------------------------------------------
// fp32 -> bf16 hi/lo split
// ---------------------------------------------------------------------------
__global__ void split_kernel(const float* __restrict__ X, __nv_bfloat16* __restrict__ Xh,
                             __nv_bfloat16* __restrict__ Xl, int n4)
{
    int i = blockIdx.x * blockDim.x + threadIdx.x;
    if (i >= n4) return;
    float4 v = ((const float4*)X)[i];
    float a[4] = {v.x, v.y, v.z, v.w};
    __nv_bfloat16 h[4], l[4];
    #pragma unroll
    for (int j = 0; j < 4; j++) {
        h[j] = __float2bfloat16(a[j]);
        l[j] = __float2bfloat16(a[j] - __bfloat162float(h[j]));
    }
    __nv_bfloat162* Hp = (__nv_bfloat162*)(Xh + 4 * (size_t)i);
    __nv_bfloat162* Lp = (__nv_bfloat162*)(Xl + 4 * (size_t)i);
    Hp[0] = __nv_bfloat162(h[0], h[1]); Hp[1] = __nv_bfloat162(h[2], h[3]);
    Lp[0] = __nv_bfloat162(l[0], l[1]); Lp[1] = __nv_bfloat162(l[2], l[3]);
}

// ---------------------------------------------------------------------------
// W[K][N] -> Th/Tl[N][K] bf16 hi/lo (transpose + split)
// ---------------------------------------------------------------------------
__global__ void transpose_split_kernel(const float* __restrict__ W, __nv_bfloat16* __restrict__ Th,
                                       __nv_bfloat16* __restrict__ Tl, int K, int N)
{
    __shared__ float tile[32][33];
    int n0 = blockIdx.x * 32, k0 = blockIdx.y * 32;
    int tx = threadIdx.x, ty = threadIdx.y;
    #pragma unroll
    for (int j = ty; j < 32; j += 8)
        tile[j][tx] = W[(size_t)(k0 + j) * N + n0 + tx];
    __syncthreads();
    #pragma unroll
    for (int j = ty; j < 32; j += 8) {
        float v = tile[tx][j];
        __nv_bfloat16 h = __float2bfloat16(v);
        __nv_bfloat16 l = __float2bfloat16(v - __bfloat162float(h));
        size_t o = (size_t)(n0 + j) * K + k0 + tx;
        Th[o] = h; Tl[o] = l;
    }
}

// ---------------------------------------------------------------------------
// HMMA bf16-split GEMM: 128x128x32 CTA tile, 8 warps of 64x32, 2-stage
// cp.async double buffer, 2 CTAs/SM. SPLIT=0: fp32 out. SPLIT=1: bf16 hi/lo
// out; columns >= 1024 are routed to the D pair (fused K|V projection).
// ---------------------------------------------------------------------------
#define BM 128
#define BN 128
#define BK 32
#define PITCH 80
#define TILE_B (128 * PITCH)        // 10240
#define STAGE  (4 * TILE_B)         // 40960
#define GEMM_SMEM (2 * STAGE)       // 81920

template<int SPLIT>
__global__ void __launch_bounds__(256, 2)
gemm_hmma_kernel(const __nv_bfloat16* __restrict__ Ah, const __nv_bfloat16* __restrict__ Al,
                 const __nv_bfloat16* __restrict__ Bh, const __nv_bfloat16* __restrict__ Bl,
                 float* __restrict__ C, __nv_bfloat16* __restrict__ Ch,
                 __nv_bfloat16* __restrict__ Cl, __nv_bfloat16* __restrict__ Dh,
                 __nv_bfloat16* __restrict__ Dl, int K)
{
    extern __shared__ __align__(128) char sm[];
    const uint32_t sb = smem_u32(sm);
    const int t = threadIdx.x, wid = t >> 5, lane = t & 31;
    const int m0 = blockIdx.y * BM, n0 = blockIdx.x * BN;
    const int NC = K / BK;
    const int wr = wid & 1, wc = wid >> 1;

    const int lr0 = t >> 2;
    const int lch = t & 3;

    const int g = lane >> 3, lrw = lane & 7;
    const uint32_t a_off = (uint32_t)(((g & 1) * 8 + lrw) * PITCH + (g >> 1) * 16);
    const uint32_t b_off = (uint32_t)(((g >> 1) * 8 + lrw) * PITCH + (g & 1) * 16);

    float acc[4][4][4];
    #pragma unroll
    for (int mt = 0; mt < 4; mt++)
        #pragma unroll
        for (int ng = 0; ng < 4; ng++)
            #pragma unroll
            for (int q = 0; q < 4; q++) acc[mt][ng][q] = 0.0f;

    auto issue = [&](int c) {
        const int buf = c & 1;
        const uint32_t stg = sb + buf * STAGE;
        const int kt = c * BK;
        #pragma unroll
        for (int i = 0; i < 2; i++) {
            const int r = lr0 + i * 64;
            const uint32_t doff = (uint32_t)(r * PITCH + lch * 16);
            const size_t sa = (size_t)(m0 + r) * K + kt + lch * 8;
            const size_t sbi = (size_t)(n0 + r) * K + kt + lch * 8;
            CP_ASYNC16(stg + doff,               Ah + sa);
            CP_ASYNC16(stg + TILE_B + doff,      Al + sa);
            CP_ASYNC16(stg + 2 * TILE_B + doff,  Bh + sbi);
            CP_ASYNC16(stg + 3 * TILE_B + doff,  Bl + sbi);
        }
        CP_COMMIT();
    };

    issue(0);

    for (int c = 0; c < NC; c++) {
        if (c + 1 < NC) { issue(c + 1); CP_WAIT(1); }
        else            { CP_WAIT(0); }
        __syncthreads();

        const uint32_t stg = sb + (c & 1) * STAGE;
        const uint32_t aH = stg + (uint32_t)(wr * 64) * PITCH;
        const uint32_t aL = aH + TILE_B;
        const uint32_t bH = stg + 2 * TILE_B + (uint32_t)(wc * 32) * PITCH;
        const uint32_t bL = bH + TILE_B;

        #pragma unroll
        for (int ks = 0; ks < 2; ks++) {
            const uint32_t kb = (uint32_t)(ks * 32);
            uint32_t fAh[4][4], fAl[4][4], fBh[4][2], fBl[4][2];
            #pragma unroll
            for (int mt = 0; mt < 4; mt++) {
                uint32_t ad = aH + (uint32_t)(mt * 16) * PITCH + kb + a_off;
                LDM_X4(fAh[mt][0], fAh[mt][1], fAh[mt][2], fAh[mt][3], ad);
                uint32_t ad2 = aL + (uint32_t)(mt * 16) * PITCH + kb + a_off;
                LDM_X4(fAl[mt][0], fAl[mt][1], fAl[mt][2], fAl[mt][3], ad2);
            }
            #pragma unroll
            for (int nt = 0; nt < 2; nt++) {
                uint32_t bd = bH + (uint32_t)(nt * 16) * PITCH + kb + b_off;
                uint32_t r0, r1, r2, r3;
                LDM_X4(r0, r1, r2, r3, bd);
                fBh[nt * 2][0] = r0; fBh[nt * 2][1] = r1;
                fBh[nt * 2 + 1][0] = r2; fBh[nt * 2 + 1][1] = r3;
                uint32_t bd2 = bL + (uint32_t)(nt * 16) * PITCH + kb + b_off;
                LDM_X4(r0, r1, r2, r3, bd2);
                fBl[nt * 2][0] = r0; fBl[nt * 2][1] = r1;
                fBl[nt * 2 + 1][0] = r2; fBl[nt * 2 + 1][1] = r3;
            }
            #pragma unroll
            for (int mt = 0; mt < 4; mt++) {
                #pragma unroll
                for (int ng = 0; ng < 4; ng++) {
                    MMA_BF16(acc[mt][ng], fAh[mt], fBh[ng]);
                    MMA_BF16(acc[mt][ng], fAh[mt], fBl[ng]);
                    MMA_BF16(acc[mt][ng], fAl[mt], fBh[ng]);
                }
            }
        }
        __syncthreads();
    }

    const int row0 = m0 + wr * 64 + lane / 4;
    const int col0 = wc * 32 + (lane % 4) * 2;
    #pragma unroll
    for (int mt = 0; mt < 4; mt++) {
        #pragma unroll
        for (int ng = 0; ng < 4; ng++) {
            int gc = n0 + col0 + ng * 8;
            if (SPLIT) {
                __nv_bfloat16 *Hp, *Lp;
                if (gc < 1024) { Hp = Ch; Lp = Cl; }
                else           { Hp = Dh; Lp = Dl; gc -= 1024; }
                size_t o1 = (size_t)(row0 + mt * 16) * DIM + gc;
                size_t o2 = o1 + 8 * DIM;
                uint32_t h, l;
                split2(acc[mt][ng][0], acc[mt][ng][1], h, l);
                *(uint32_t*)(Hp + o1) = h; *(uint32_t*)(Lp + o1) = l;
                split2(acc[mt][ng][2], acc[mt][ng][3], h, l);
                *(uint32_t*)(Hp + o2) = h; *(uint32_t*)(Lp + o2) = l;
            } else {
                size_t o1 = (size_t)(row0 + mt * 16) * DIM + gc;
                size_t o2 = o1 + 8 * DIM;
                *(float2*)(C + o1) = make_float2(acc[mt][ng][0], acc[mt][ng][1]);
                *(float2*)(C + o2) = make_float2(acc[mt][ng][2], acc[mt][ng][3]);
            }
        }
    }
}

// ---------------------------------------------------------------------------
// HMMA flash-attention (R9-proven): 128 Q-rows/CTA, 8 warps x 16 rows x all
// keys, two 128-key halves, online softmax with full quad-reduced row sums.
// ---------------------------------------------------------------------------
#define AP 144
#define OFF_QH 0
#define OFF_QL 18432
#define OFF_KH 36864
#define OFF_KL 73728
#define OFF_VH 110592
#define OFF_VL 147456
#define OFF_MS 184320
#define ATTN_SMEM 185344

__global__ void __launch_bounds__(256, 1)
attn_hmma_kernel(const __nv_bfloat16* __restrict__ Qh, const __nv_bfloat16* __restrict__ Ql,
                 const __nv_bfloat16* __restrict__ Kh, const __nv_bfloat16* __restrict__ Kl,
                 const __nv_bfloat16* __restrict__ Vh, const __nv_bfloat16* __restrict__ Vl,
                 const int* __restrict__ maskp,
                 __nv_bfloat16* __restrict__ Oh, __nv_bfloat16* __restrict__ Ol)
{
    extern __shared__ __align__(128) char smc[];
    const uint32_t sb = smem_u32(smc);
    int* Msm = (int*)(smc + OFF_MS);

    const int t = threadIdx.x, wid = t >> 5, lane = t & 31;
    const int b = blockIdx.y >> 4, h = blockIdx.y & 15;
    const int n0 = blockIdx.x * 128;

    #pragma unroll
    for (int i = 0; i < 4; i++) {
        int idx = t + i * 256;
        int r = idx >> 3, ch = idx & 7;
        uint32_t doff = (uint32_t)(r * AP + ch * 16);
        size_t src = (size_t)(b * SEQ_N + n0 + r) * DIM + h * HD + ch * 8;
        CP_ASYNC16(sb + OFF_QH + doff, Qh + src);
        CP_ASYNC16(sb + OFF_QL + doff, Ql + src);
    }
    #pragma unroll
    for (int i = 0; i < 8; i++) {
        int idx = t + i * 256;
        int r = idx >> 3, ch = idx & 7;
        uint32_t doff = (uint32_t)(r * AP + ch * 16);
        size_t src = (size_t)(b * SEQ_M + r) * DIM + h * HD + ch * 8;
        CP_ASYNC16(sb + OFF_KH + doff, Kh + src);
        CP_ASYNC16(sb + OFF_KL + doff, Kl + src);
        CP_ASYNC16(sb + OFF_VH + doff, Vh + src);
        CP_ASYNC16(sb + OFF_VL + doff, Vl + src);
    }
    CP_COMMIT();
    Msm[t] = maskp[b * SEQ_M + t];
    CP_WAIT(0);
    __syncthreads();

    const int wm = wid;
    const int g = lane >> 3, lrw = lane & 7;
    const uint32_t a_off = (uint32_t)(((g & 1) * 8 + lrw) * AP + (g >> 1) * 16);
    const uint32_t b_off = (uint32_t)(((g >> 1) * 8 + lrw) * AP + (g & 1) * 16);

    float o[8][4];
    #pragma unroll
    for (int j = 0; j < 8; j++)
        #pragma unroll
        for (int q = 0; q < 4; q++) o[j][q] = 0.0f;
    float M1 = -INFINITY, M2 = -INFINITY, S1 = 0.0f, S2 = 0.0f;

    const float scale = 0.125f;

    #pragma unroll
    for (int hf = 0; hf < 2; hf++) {
        float acc[16][4];
        #pragma unroll
        for (int j = 0; j < 16; j++)
            #pragma unroll
            for (int q = 0; q < 4; q++) acc[j][q] = 0.0f;

        #pragma unroll
        for (int ks = 0; ks < 4; ks++) {
            const uint32_t kb = (uint32_t)(ks * 32);
            uint32_t fAh[4], fAl[4];
            LDM_X4(fAh[0], fAh[1], fAh[2], fAh[3],
                   sb + OFF_QH + (uint32_t)(wm * 16) * AP + kb + a_off);
            LDM_X4(fAl[0], fAl[1], fAl[2], fAl[3],
                   sb + OFF_QL + (uint32_t)(wm * 16) * AP + kb + a_off);
            #pragma unroll
            for (int nt = 0; nt < 8; nt++) {
                uint32_t krow = (uint32_t)(hf * 128 + nt * 16) * AP + kb + b_off;
                uint32_t h0, h1, h2, h3, l0, l1, l2, l3;
                LDM_X4(h0, h1, h2, h3, sb + OFF_KH + krow);
                LDM_X4(l0, l1, l2, l3, sb + OFF_KL + krow);
                uint32_t bh0[2] = {h0, h1}, bh1[2] = {h2, h3};
                uint32_t bl0[2] = {l0, l1}, bl1[2] = {l2, l3};
                MMA_BF16(acc[nt * 2],     fAh, bh0);
                MMA_BF16(acc[nt * 2],     fAh, bl0);
                MMA_BF16(acc[nt * 2],     fAl, bh0);
                MMA_BF16(acc[nt * 2 + 1], fAh, bh1);
                MMA_BF16(acc[nt * 2 + 1], fAh, bl1);
                MMA_BF16(acc[nt * 2 + 1], fAl, bh1);
            }
        }

        float m1 = -INFINITY, m2 = -INFINITY;
        #pragma unroll
        for (int j = 0; j < 16; j++) {
            int cb = hf * 128 + j * 8 + (lane & 3) * 2;
            bool k0 = Msm[cb] != 0, k1 = Msm[cb + 1] != 0;
            acc[j][0] = k0 ? acc[j][0] * scale : -1e30f;
            acc[j][1] = k1 ? acc[j][1] * scale : -1e30f;
            acc[j][2] = k0 ? acc[j][2] * scale : -1e30f;
            acc[j][3] = k1 ? acc[j][3] * scale : -1e30f;
            m1 = fmaxf(m1, fmaxf(acc[j][0], acc[j][1]));
            m2 = fmaxf(m2, fmaxf(acc[j][2], acc[j][3]));
        }
        m1 = fmaxf(m1, __shfl_xor_sync(0xffffffffu, m1, 1));
        m1 = fmaxf(m1, __shfl_xor_sync(0xffffffffu, m1, 2));
        m2 = fmaxf(m2, __shfl_xor_sync(0xffffffffu, m2, 1));
        m2 = fmaxf(m2, __shfl_xor_sync(0xffffffffu, m2, 2));

        float M1n = fmaxf(M1, m1), M2n = fmaxf(M2, m2);
        float sc1 = __expf(M1 - M1n), sc2 = __expf(M2 - M2n);
        #pragma unroll
        for (int j = 0; j < 8; j++) {
            o[j][0] *= sc1; o[j][1] *= sc1;
            o[j][2] *= sc2; o[j][3] *= sc2;
        }
        S1 *= sc1; S2 *= sc2;
        M1 = M1n; M2 = M2n;

        float s1 = 0.0f, s2 = 0.0f;
        #pragma unroll
        for (int j = 0; j < 16; j++) {
            acc[j][0] = __expf(acc[j][0] - M1);
            acc[j][1] = __expf(acc[j][1] - M1);
            acc[j][2] = __expf(acc[j][2] - M2);
            acc[j][3] = __expf(acc[j][3] - M2);
            s1 += acc[j][0] + acc[j][1];
            s2 += acc[j][2] + acc[j][3];
        }
        s1 += __shfl_xor_sync(0xffffffffu, s1, 1);
        s1 += __shfl_xor_sync(0xffffffffu, s1, 2);
        s2 += __shfl_xor_sync(0xffffffffu, s2, 1);
        s2 += __shfl_xor_sync(0xffffffffu, s2, 2);
        S1 += s1; S2 += s2;

        #pragma unroll
        for (int kk = 0; kk < 8; kk++) {
            const int j0 = kk * 2, j1 = j0 + 1;
            uint32_t ph[4], pl[4];
            split2(acc[j0][0], acc[j0][1], ph[0], pl[0]);
            split2(acc[j0][2], acc[j0][3], ph[1], pl[1]);
            split2(acc[j1][0], acc[j1][1], ph[2], pl[2]);
            split2(acc[j1][2], acc[j1][3], ph[3], pl[3]);

            const uint32_t vrow = (uint32_t)(hf * 128 + kk * 16 + (g & 1) * 8 + lrw) * AP;
            #pragma unroll
            for (int ngp = 0; ngp < 4; ngp++) {
                const uint32_t vcol = (uint32_t)(((g >> 1) * 8 + ngp * 16) * 2);
                uint32_t h0, h1, h2, h3, l0, l1, l2, l3;
                LDM_X4T(h0, h1, h2, h3, sb + OFF_VH + vrow + vcol);
                LDM_X4T(l0, l1, l2, l3, sb + OFF_VL + vrow + vcol);
                uint32_t vh0[2] = {h0, h1}, vh1[2] = {h2, h3};
                uint32_t vl0[2] = {l0, l1}, vl1[2] = {l2, l3};
                MMA_BF16(o[ngp * 2],     ph, vh0);
                MMA_BF16(o[ngp * 2],     ph, vl0);
                MMA_BF16(o[ngp * 2],     pl, vh0);
                MMA_BF16(o[ngp * 2 + 1], ph, vh1);
                MMA_BF16(o[ngp * 2 + 1], ph, vl1);
                MMA_BF16(o[ngp * 2 + 1], pl, vh1);
            }
        }
    }

    const float inv1 = 1.0f / S1, inv2 = 1.0f / S2;
    const int r1 = wm * 16 + (lane >> 2), r2 = r1 + 8;
    #pragma unroll
    for (int j = 0; j < 8; j++) {
        int col = j * 8 + (lane & 3) * 2;
        size_t go1 = (size_t)(b * SEQ_N + n0 + r1) * DIM + h * HD + col;
        size_t go2 = (size_t)(b * SEQ_N + n0 + r2) * DIM + h * HD + col;
        uint32_t hh, ll;
        split2(o[j][0] * inv1, o[j][1] * inv1, hh, ll);
        *(uint32_t*)(Oh + go1) = hh; *(uint32_t*)(Ol + go1) = ll;
        split2(o[j][2] * inv2, o[j][3] * inv2, hh, ll);
        *(uint32_t*)(Oh + go2) = hh; *(uint32_t*)(Ol + go2) = ll;
    }
}

// ---------------------------------------------------------------------------
// Host launcher
// ---------------------------------------------------------------------------
extern "C" void kernel_launch(void* const* d_in, const int* in_sizes, int n_in,
                              void* d_out, int out_size)
{
    const float* x    = (const float*)d_in[0];
    const float* ctx  = (const float*)d_in[1];
    const int*   mask = (const int*)d_in[2];
    const float* Wq   = (const float*)d_in[3];
    const float* Wk   = (const float*)d_in[4];
    const float* Wv   = (const float*)d_in[5];
    const float* Wo   = (const float*)d_in[6];
    float*       out  = (float*)d_out;

    __nv_bfloat16 *Ahp, *Alp, *Chp, *Clp, *Bhp, *Blp, *Qhp, *Qlp, *Khp, *Klp, *Vhp, *Vlp;
    cudaGetSymbolAddress((void**)&Ahp, g_Ah);
    cudaGetSymbolAddress((void**)&Alp, g_Al);
    cudaGetSymbolAddress((void**)&Chp, g_Ch);
    cudaGetSymbolAddress((void**)&Clp, g_Cl);
    cudaGetSymbolAddress((void**)&Bhp, g_Bh);
    cudaGetSymbolAddress((void**)&Blp, g_Bl);
    cudaGetSymbolAddress((void**)&Qhp, g_Qh);
    cudaGetSymbolAddress((void**)&Qlp, g_Ql);
    cudaGetSymbolAddress((void**)&Khp, g_Kh);
    cudaGetSymbolAddress((void**)&Klp, g_Kl);
    cudaGetSymbolAddress((void**)&Vhp, g_Vh);
    cudaGetSymbolAddress((void**)&Vlp, g_Vl);

    cudaFuncSetAttribute(gemm_hmma_kernel<0>, cudaFuncAttributeMaxDynamicSharedMemorySize, GEMM_SMEM);
    cudaFuncSetAttribute(gemm_hmma_kernel<1>, cudaFuncAttributeMaxDynamicSharedMemorySize, GEMM_SMEM);
    cudaFuncSetAttribute(attn_hmma_kernel, cudaFuncAttributeMaxDynamicSharedMemorySize, ATTN_SMEM);

    const int n4x = ROWS_X * DIM / 4;
    const int n4c = ROWS_C * CTX_DIM / 4;
    dim3 tb32(32, 8);

    // Q projection -> split bf16
    split_kernel<<<n4x / 256, 256>>>(x, Ahp, Alp, n4x);
    transpose_split_kernel<<<dim3(DIM / 32, DIM / 32), tb32>>>(Wq, Bhp, Blp, DIM, DIM);
    gemm_hmma_kernel<1><<<dim3(DIM / BN, ROWS_X / BM), 256, GEMM_SMEM>>>(
        Ahp, Alp, Bhp, Blp, nullptr, Qhp, Qlp, nullptr, nullptr, DIM);

    // fused K|V projection -> split bf16 (B rows 0..1023 = Wk^T, 1024..2047 = Wv^T)
    split_kernel<<<n4c / 256, 256>>>(ctx, Chp, Clp, n4c);
    transpose_split_kernel<<<dim3(DIM / 32, CTX_DIM / 32), tb32>>>(Wk, Bhp, Blp, CTX_DIM, DIM);
    transpose_split_kernel<<<dim3(DIM / 32, CTX_DIM / 32), tb32>>>(
        Wv, Bhp + 1024 * CTX_DIM, Blp + 1024 * CTX_DIM, CTX_DIM, DIM);
    gemm_hmma_kernel<1><<<dim3(2048 / BN, ROWS_C / BM), 256, GEMM_SMEM>>>(
        Chp, Clp, Bhp, Blp, nullptr, Khp, Klp, Vhp, Vlp, CTX_DIM);

    // Flash attention -> split bf16 into g_Ah/g_Al
    attn_hmma_kernel<<<dim3(SEQ_N / 128, BATCH * HEADS), 256, ATTN_SMEM>>>(
        Qhp, Qlp, Khp, Klp, Vhp, Vlp, mask, Ahp, Alp);

    // O projection -> fp32 final output
    transpose_split_kernel<<<dim3(DIM / 32, DIM / 32), tb32>>>(Wo, Bhp, Blp, DIM, DIM);
    gemm_hmma_kernel<0><<<dim3(DIM / BN, ROWS_X / BM), 256, GEMM_SMEM>>>(
        Ahp, Alp, Bhp, Blp, out, nullptr, nullptr, nullptr, nullptr, DIM);
}

// round 11
// speedup vs baseline: 1.2896x; 1.0261x over previous
#include <cuda_runtime.h>
#include <cuda_bf16.h>
#include <math.h>
#include <stdint.h>

// Problem constants
#define BATCH 4
#define SEQ_N 4096
#define SEQ_M 256
#define DIM 1024
#define CTX_DIM 768
#define HEADS 16
#define HD 64
#define ROWS_X (BATCH * SEQ_N)      // 16384
#define ROWS_C (BATCH * SEQ_M)      // 1024

// Scratch (device globals)
__device__ __nv_bfloat16 g_Ah[ROWS_X * DIM];
__device__ __nv_bfloat16 g_Al[ROWS_X * DIM];
__device__ __nv_bfloat16 g_Ch[ROWS_C * CTX_DIM];
__device__ __nv_bfloat16 g_Cl[ROWS_C * CTX_DIM];
__device__ __nv_bfloat16 g_Bh[2048 * 1024];
__device__ __nv_bfloat16 g_Bl[2048 * 1024];
__device__ __nv_bfloat16 g_Qh[ROWS_X * DIM];
__device__ __nv_bfloat16 g_Ql[ROWS_X * DIM];
__device__ __nv_bfloat16 g_Kh[ROWS_C * DIM];
__device__ __nv_bfloat16 g_Kl[ROWS_C * DIM];
__device__ __nv_bfloat16 g_Vh[ROWS_C * DIM];
__device__ __nv_bfloat16 g_Vl[ROWS_C * DIM];

// ---------------------------------------------------------------------------
// PTX helpers (sm_80+ portable)
// ---------------------------------------------------------------------------
__device__ __forceinline__ uint32_t smem_u32(const void* p) {
    uint32_t a;
    asm("{ .reg .u64 t; cvta.to.shared.u64 t, %1; cvt.u32.u64 %0, t; }" : "=r"(a) : "l"(p));
    return a;
}
#define CP_ASYNC16(dst, src) \
    asm volatile("cp.async.cg.shared.global [%0], [%1], 16;" :: "r"(dst), "l"(src))
#define CP_COMMIT() asm volatile("cp.async.commit_group;" ::: "memory")
#define CP_WAIT(n)  asm volatile("cp.async.wait_group %0;" :: "n"(n) : "memory")

#define LDM_X4(r0, r1, r2, r3, a) \
    asm volatile("ldmatrix.sync.aligned.m8n8.x4.shared.b16 {%0,%1,%2,%3}, [%4];" \
                 : "=r"(r0), "=r"(r1), "=r"(r2), "=r"(r3) : "r"(a))
#define LDM_X4T(r0, r1, r2, r3, a) \
    asm volatile("ldmatrix.sync.aligned.m8n8.x4.trans.shared.b16 {%0,%1,%2,%3}, [%4];" \
                 : "=r"(r0), "=r"(r1), "=r"(r2), "=r"(r3) : "r"(a))

#define MMA_BF16(d, a, b) \
    asm volatile("mma.sync.aligned.m16n8k16.row.col.f32.bf16.bf16.f32 " \
                 "{%0,%1,%2,%3},{%4,%5,%6,%7},{%8,%9},{%0,%1,%2,%3};" \
                 : "+f"((d)[0]), "+f"((d)[1]), "+f"((d)[2]), "+f"((d)[3]) \
                 : "r"((a)[0]), "r"((a)[1]), "r"((a)[2]), "r"((a)[3]), \
                   "r"((b)[0]), "r"((b)[1]))

__device__ __forceinline__ void split2(float x, float y, uint32_t& h, uint32_t& l) {
    __nv_bfloat162 hb = __float22bfloat162_rn(make_float2(x, y));
    float2 hf = __bfloat1622float2(hb);
    __nv_bfloat162 lb = __float22bfloat162_rn(make_float2(x - hf.x, y - hf.y));
    h = *(uint32_t*)&hb;
    l = *(uint32_t*)&lb;
}

// ---------------------------------------------------------------------------
// fp32 -> bf16 hi/lo split
// ---------------------------------------------------------------------------
__global__ void split_kernel(const float* __restrict__ X, __nv_bfloat16* __restrict__ Xh,
                             __nv_bfloat16* __restrict__ Xl, int n4)
{
    int i = blockIdx.x * blockDim.x + threadIdx.x;
    if (i >= n4) return;
    float4 v = ((const float4*)X)[i];
    float a[4] = {v.x, v.y, v.z, v.w};
    __nv_bfloat16 h[4], l[4];
    #pragma unroll
    for (int j = 0; j < 4; j++) {
        h[j] = __float2bfloat16(a[j]);
        l[j] = __float2bfloat16(a[j] - __bfloat162float(h[j]));
    }
    __nv_bfloat162* Hp = (__nv_bfloat162*)(Xh + 4 * (size_t)i);
    __nv_bfloat162* Lp = (__nv_bfloat162*)(Xl + 4 * (size_t)i);
    Hp[0] = __nv_bfloat162(h[0], h[1]); Hp[1] = __nv_bfloat162(h[2], h[3]);
    Lp[0] = __nv_bfloat162(l[0], l[1]); Lp[1] = __nv_bfloat162(l[2], l[3]);
}

// ---------------------------------------------------------------------------
// W[K][N] -> Th/Tl[N][K] bf16 hi/lo (transpose + split)
// ---------------------------------------------------------------------------
__global__ void transpose_split_kernel(const float* __restrict__ W, __nv_bfloat16* __restrict__ Th,
                                       __nv_bfloat16* __restrict__ Tl, int K, int N)
{
    __shared__ float tile[32][33];
    int n0 = blockIdx.x * 32, k0 = blockIdx.y * 32;
    int tx = threadIdx.x, ty = threadIdx.y;
    #pragma unroll
    for (int j = ty; j < 32; j += 8)
        tile[j][tx] = W[(size_t)(k0 + j) * N + n0 + tx];
    __syncthreads();
    #pragma unroll
    for (int j = ty; j < 32; j += 8) {
        float v = tile[tx][j];
        __nv_bfloat16 h = __float2bfloat16(v);
        __nv_bfloat16 l = __float2bfloat16(v - __bfloat162float(h));
        size_t o = (size_t)(n0 + j) * K + k0 + tx;
        Th[o] = h; Tl[o] = l;
    }
}

// ---------------------------------------------------------------------------
// HMMA bf16-split GEMM (R10-proven): 128x128x32 CTA tile, 8 warps of 64x32,
// 2-stage cp.async double buffer, 2 CTAs/SM. SPLIT=0: fp32 out. SPLIT=1:
// bf16 hi/lo out; cols >= 1024 routed to D pair (fused K|V projection).
// ---------------------------------------------------------------------------
#define BM 128
#define BN 128
#define BK 32
#define PITCH 80
#define TILE_B (128 * PITCH)        // 10240
#define STAGE  (4 * TILE_B)         // 40960
#define GEMM_SMEM (2 * STAGE)       // 81920

template<int SPLIT>
__global__ void __launch_bounds__(256, 2)
gemm_hmma_kernel(const __nv_bfloat16* __restrict__ Ah, const __nv_bfloat16* __restrict__ Al,
                 const __nv_bfloat16* __restrict__ Bh, const __nv_bfloat16* __restrict__ Bl,
                 float* __restrict__ C, __nv_bfloat16* __restrict__ Ch,
                 __nv_bfloat16* __restrict__ Cl, __nv_bfloat16* __restrict__ Dh,
                 __nv_bfloat16* __restrict__ Dl, int K)
{
    extern __shared__ __align__(128) char sm[];
    const uint32_t sb = smem_u32(sm);
    const int t = threadIdx.x, wid = t >> 5, lane = t & 31;
    const int m0 = blockIdx.y * BM, n0 = blockIdx.x * BN;
    const int NC = K / BK;
    const int wr = wid & 1, wc = wid >> 1;

    const int lr0 = t >> 2;
    const int lch = t & 3;

    const int g = lane >> 3, lrw = lane & 7;
    const uint32_t a_off = (uint32_t)(((g & 1) * 8 + lrw) * PITCH + (g >> 1) * 16);
    const uint32_t b_off = (uint32_t)(((g >> 1) * 8 + lrw) * PITCH + (g & 1) * 16);

    float acc[4][4][4];
    #pragma unroll
    for (int mt = 0; mt < 4; mt++)
        #pragma unroll
        for (int ng = 0; ng < 4; ng++)
            #pragma unroll
            for (int q = 0; q < 4; q++) acc[mt][ng][q] = 0.0f;

    auto issue = [&](int c) {
        const int buf = c & 1;
        const uint32_t stg = sb + buf * STAGE;
        const int kt = c * BK;
        #pragma unroll
        for (int i = 0; i < 2; i++) {
            const int r = lr0 + i * 64;
            const uint32_t doff = (uint32_t)(r * PITCH + lch * 16);
            const size_t sa = (size_t)(m0 + r) * K + kt + lch * 8;
            const size_t sbi = (size_t)(n0 + r) * K + kt + lch * 8;
            CP_ASYNC16(stg + doff,               Ah + sa);
            CP_ASYNC16(stg + TILE_B + doff,      Al + sa);
            CP_ASYNC16(stg + 2 * TILE_B + doff,  Bh + sbi);
            CP_ASYNC16(stg + 3 * TILE_B + doff,  Bl + sbi);
        }
        CP_COMMIT();
    };

    issue(0);

    for (int c = 0; c < NC; c++) {
        if (c + 1 < NC) { issue(c + 1); CP_WAIT(1); }
        else            { CP_WAIT(0); }
        __syncthreads();

        const uint32_t stg = sb + (c & 1) * STAGE;
        const uint32_t aH = stg + (uint32_t)(wr * 64) * PITCH;
        const uint32_t aL = aH + TILE_B;
        const uint32_t bH = stg + 2 * TILE_B + (uint32_t)(wc * 32) * PITCH;
        const uint32_t bL = bH + TILE_B;

        #pragma unroll
        for (int ks = 0; ks < 2; ks++) {
            const uint32_t kb = (uint32_t)(ks * 32);
            uint32_t fAh[4][4], fAl[4][4], fBh[4][2], fBl[4][2];
            #pragma unroll
            for (int mt = 0; mt < 4; mt++) {
                uint32_t ad = aH + (uint32_t)(mt * 16) * PITCH + kb + a_off;
                LDM_X4(fAh[mt][0], fAh[mt][1], fAh[mt][2], fAh[mt][3], ad);
                uint32_t ad2 = aL + (uint32_t)(mt * 16) * PITCH + kb + a_off;
                LDM_X4(fAl[mt][0], fAl[mt][1], fAl[mt][2], fAl[mt][3], ad2);
            }
            #pragma unroll
            for (int nt = 0; nt < 2; nt++) {
                uint32_t bd = bH + (uint32_t)(nt * 16) * PITCH + kb + b_off;
                uint32_t r0, r1, r2, r3;
                LDM_X4(r0, r1, r2, r3, bd);
                fBh[nt * 2][0] = r0; fBh[nt * 2][1] = r1;
                fBh[nt * 2 + 1][0] = r2; fBh[nt * 2 + 1][1] = r3;
                uint32_t bd2 = bL + (uint32_t)(nt * 16) * PITCH + kb + b_off;
                LDM_X4(r0, r1, r2, r3, bd2);
                fBl[nt * 2][0] = r0; fBl[nt * 2][1] = r1;
                fBl[nt * 2 + 1][0] = r2; fBl[nt * 2 + 1][1] = r3;
            }
            #pragma unroll
            for (int mt = 0; mt < 4; mt++) {
                #pragma unroll
                for (int ng = 0; ng < 4; ng++) {
                    MMA_BF16(acc[mt][ng], fAh[mt], fBh[ng]);
                    MMA_BF16(acc[mt][ng], fAh[mt], fBl[ng]);
                    MMA_BF16(acc[mt][ng], fAl[mt], fBh[ng]);
                }
            }
        }
        __syncthreads();
    }

    const int row0 = m0 + wr * 64 + lane / 4;
    const int col0 = wc * 32 + (lane % 4) * 2;
    #pragma unroll
    for (int mt = 0; mt < 4; mt++) {
        #pragma unroll
        for (int ng = 0; ng < 4; ng++) {
            int gc = n0 + col0 + ng * 8;
            if (SPLIT) {
                __nv_bfloat16 *Hp, *Lp;
                if (gc < 1024) { Hp = Ch; Lp = Cl; }
                else           { Hp = Dh; Lp = Dl; gc -= 1024; }
                size_t o1 = (size_t)(row0 + mt * 16) * DIM + gc;
                size_t o2 = o1 + 8 * DIM;
                uint32_t h, l;
                split2(acc[mt][ng][0], acc[mt][ng][1], h, l);
                *(uint32_t*)(Hp + o1) = h; *(uint32_t*)(Lp + o1) = l;
                split2(acc[mt][ng][2], acc[mt][ng][3], h, l);
                *(uint32_t*)(Hp + o2) = h; *(uint32_t*)(Lp + o2) = l;
            } else {
                size_t o1 = (size_t)(row0 + mt * 16) * DIM + gc;
                size_t o2 = o1 + 8 * DIM;
                *(float2*)(C + o1) = make_float2(acc[mt][ng][0], acc[mt][ng][1]);
                *(float2*)(C + o2) = make_float2(acc[mt][ng][2], acc[mt][ng][3]);
            }
        }
    }
}

// ---------------------------------------------------------------------------
// HMMA flash-attention, chunked for 2 CTAs/SM:
// 128 Q-rows/CTA, 8 warps x 16 rows x all keys; keys streamed in FOUR 64-key
// chunks through double-buffered K/V chunk tiles (cp.async FIFO pacing).
// Fragment/index math identical to the R9-proven kernel (AP=144 padding).
// smem: Q 36864 + K bufs 2x18432 + V bufs 2x18432 + mask = 111616 < 114688.
// ---------------------------------------------------------------------------
#define AP 144
#define OFF_QH 0
#define OFF_QL 18432
#define OFF_KA 36864
#define OFF_KB 55296
#define OFF_VA 73728
#define OFF_VB 92160
#define OFF_MS 110592
#define ATTN_SMEM 111616
#define KHALF 9216                  // 64 rows * 144B (hi part; lo at +9216)

__global__ void __launch_bounds__(256, 2)
attn_hmma_kernel(const __nv_bfloat16* __restrict__ Qh, const __nv_bfloat16* __restrict__ Ql,
                 const __nv_bfloat16* __restrict__ Kh, const __nv_bfloat16* __restrict__ Kl,
                 const __nv_bfloat16* __restrict__ Vh, const __nv_bfloat16* __restrict__ Vl,
                 const int* __restrict__ maskp,
                 __nv_bfloat16* __restrict__ Oh, __nv_bfloat16* __restrict__ Ol)
{
    extern __shared__ __align__(128) char smc[];
    const uint32_t sb = smem_u32(smc);
    int* Msm = (int*)(smc + OFF_MS);

    const int t = threadIdx.x, wid = t >> 5, lane = t & 31;
    const int b = blockIdx.y >> 4, h = blockIdx.y & 15;
    const int n0 = blockIdx.x * 128;

    // --- async producers -------------------------------------------------
    auto issueQ = [&]() {
        #pragma unroll
        for (int i = 0; i < 4; i++) {
            int idx = t + i * 256;              // < 1024
            int r = idx >> 3, ch = idx & 7;
            uint32_t doff = (uint32_t)(r * AP + ch * 16);
            size_t src = (size_t)(b * SEQ_N + n0 + r) * DIM + h * HD + ch * 8;
            CP_ASYNC16(sb + OFF_QH + doff, Qh + src);
            CP_ASYNC16(sb + OFF_QL + doff, Ql + src);
        }
        CP_COMMIT();
    };
    auto issueK = [&](int c, uint32_t off) {
        #pragma unroll
        for (int i = 0; i < 2; i++) {
            int idx = t + i * 256;              // < 512
            int r = idx >> 3, ch = idx & 7;
            uint32_t doff = (uint32_t)(r * AP + ch * 16);
            size_t src = (size_t)(b * SEQ_M + c * 64 + r) * DIM + h * HD + ch * 8;
            CP_ASYNC16(sb + off + doff,         Kh + src);
            CP_ASYNC16(sb + off + KHALF + doff, Kl + src);
        }
        CP_COMMIT();
    };
    auto issueV = [&](int c, uint32_t off) {
        #pragma unroll
        for (int i = 0; i < 2; i++) {
            int idx = t + i * 256;
            int r = idx >> 3, ch = idx & 7;
            uint32_t doff = (uint32_t)(r * AP + ch * 16);
            size_t src = (size_t)(b * SEQ_M + c * 64 + r) * DIM + h * HD + ch * 8;
            CP_ASYNC16(sb + off + doff,         Vh + src);
            CP_ASYNC16(sb + off + KHALF + doff, Vl + src);
        }
        CP_COMMIT();
    };

    // groups (FIFO): Q, K0, V0, K1, V1
    issueQ();
    issueK(0, OFF_KA); issueV(0, OFF_VA);
    issueK(1, OFF_KB); issueV(1, OFF_VB);
    Msm[t] = maskp[b * SEQ_M + t];

    const int wm = wid;
    const int g = lane >> 3, lrw = lane & 7;
    const uint32_t a_off = (uint32_t)(((g & 1) * 8 + lrw) * AP + (g >> 1) * 16);
    const uint32_t b_off = (uint32_t)(((g >> 1) * 8 + lrw) * AP + (g & 1) * 16);

    float o[8][4];
    #pragma unroll
    for (int j = 0; j < 8; j++)
        #pragma unroll
        for (int q = 0; q < 4; q++) o[j][q] = 0.0f;
    float M1 = -INFINITY, M2 = -INFINITY, S1 = 0.0f, S2 = 0.0f;
    float acc[8][4];
    const float scale = 0.125f;

    // S for one 64-key chunk held at smem offset ko (hi; lo at +KHALF)
    auto computeS = [&](uint32_t ko) {
        #pragma unroll
        for (int j = 0; j < 8; j++)
            #pragma unroll
            for (int q = 0; q < 4; q++) acc[j][q] = 0.0f;
        #pragma unroll
        for (int ks = 0; ks < 4; ks++) {
            const uint32_t kb = (uint32_t)(ks * 32);
            uint32_t fAh[4], fAl[4];
            LDM_X4(fAh[0], fAh[1], fAh[2], fAh[3],
                   sb + OFF_QH + (uint32_t)(wm * 16) * AP + kb + a_off);
            LDM_X4(fAl[0], fAl[1], fAl[2], fAl[3],
                   sb + OFF_QL + (uint32_t)(wm * 16) * AP + kb + a_off);
            #pragma unroll
            for (int nt = 0; nt < 4; nt++) {
                uint32_t krow = (uint32_t)(nt * 16) * AP + kb + b_off;
                uint32_t h0, h1, h2, h3, l0, l1, l2, l3;
                LDM_X4(h0, h1, h2, h3, sb + ko + krow);
                LDM_X4(l0, l1, l2, l3, sb + ko + KHALF + krow);
                uint32_t bh0[2] = {h0, h1}, bh1[2] = {h2, h3};
                uint32_t bl0[2] = {l0, l1}, bl1[2] = {l2, l3};
                MMA_BF16(acc[nt * 2],     fAh, bh0);
                MMA_BF16(acc[nt * 2],     fAh, bl0);
                MMA_BF16(acc[nt * 2],     fAl, bh0);
                MMA_BF16(acc[nt * 2 + 1], fAh, bh1);
                MMA_BF16(acc[nt * 2 + 1], fAh, bl1);
                MMA_BF16(acc[nt * 2 + 1], fAl, bh1);
            }
        }
    };

    // mask+scale+online softmax + PV for the chunk at V offset vo
    auto softmaxPV = [&](int ci, uint32_t vo) {
        float m1 = -INFINITY, m2 = -INFINITY;
        #pragma unroll
        for (int j = 0; j < 8; j++) {
            int cb = ci * 64 + j * 8 + (lane & 3) * 2;
            bool k0 = Msm[cb] != 0, k1 = Msm[cb + 1] != 0;
            acc[j][0] = k0 ? acc[j][0] * scale : -1e30f;
            acc[j][1] = k1 ? acc[j][1] * scale : -1e30f;
            acc[j][2] = k0 ? acc[j][2] * scale : -1e30f;
            acc[j][3] = k1 ? acc[j][3] * scale : -1e30f;
            m1 = fmaxf(m1, fmaxf(acc[j][0], acc[j][1]));
            m2 = fmaxf(m2, fmaxf(acc[j][2], acc[j][3]));
        }
        m1 = fmaxf(m1, __shfl_xor_sync(0xffffffffu, m1, 1));
        m1 = fmaxf(m1, __shfl_xor_sync(0xffffffffu, m1, 2));
        m2 = fmaxf(m2, __shfl_xor_sync(0xffffffffu, m2, 1));
        m2 = fmaxf(m2, __shfl_xor_sync(0xffffffffu, m2, 2));

        float M1n = fmaxf(M1, m1), M2n = fmaxf(M2, m2);
        float sc1 = __expf(M1 - M1n), sc2 = __expf(M2 - M2n);
        #pragma unroll
        for (int j = 0; j < 8; j++) {
            o[j][0] *= sc1; o[j][1] *= sc1;
            o[j][2] *= sc2; o[j][3] *= sc2;
        }
        S1 *= sc1; S2 *= sc2;
        M1 = M1n; M2 = M2n;

        float s1 = 0.0f, s2 = 0.0f;
        #pragma unroll
        for (int j = 0; j < 8; j++) {
            acc[j][0] = __expf(acc[j][0] - M1);
            acc[j][1] = __expf(acc[j][1] - M1);
            acc[j][2] = __expf(acc[j][2] - M2);
            acc[j][3] = __expf(acc[j][3] - M2);
            s1 += acc[j][0] + acc[j][1];
            s2 += acc[j][2] + acc[j][3];
        }
        s1 += __shfl_xor_sync(0xffffffffu, s1, 1);
        s1 += __shfl_xor_sync(0xffffffffu, s1, 2);
        s2 += __shfl_xor_sync(0xffffffffu, s2, 1);
        s2 += __shfl_xor_sync(0xffffffffu, s2, 2);
        S1 += s1; S2 += s2;

        #pragma unroll
        for (int kk = 0; kk < 4; kk++) {
            const int j0 = kk * 2, j1 = j0 + 1;
            uint32_t ph[4], pl[4];
            split2(acc[j0][0], acc[j0][1], ph[0], pl[0]);
            split2(acc[j0][2], acc[j0][3], ph[1], pl[1]);
            split2(acc[j1][0], acc[j1][1], ph[2], pl[2]);
            split2(acc[j1][2], acc[j1][3], ph[3], pl[3]);

            const uint32_t vrow = (uint32_t)(kk * 16 + (g & 1) * 8 + lrw) * AP;
            #pragma unroll
            for (int ngp = 0; ngp < 4; ngp++) {
                const uint32_t vcol = (uint32_t)(((g >> 1) * 8 + ngp * 16) * 2);
                uint32_t h0, h1, h2, h3, l0, l1, l2, l3;
                LDM_X4T(h0, h1, h2, h3, sb + vo + vrow + vcol);
                LDM_X4T(l0, l1, l2, l3, sb + vo + KHALF + vrow + vcol);
                uint32_t vh0[2] = {h0, h1}, vh1[2] = {h2, h3};
                uint32_t vl0[2] = {l0, l1}, vl1[2] = {l2, l3};
                MMA_BF16(o[ngp * 2],     ph, vh0);
                MMA_BF16(o[ngp * 2],     ph, vl0);
                MMA_BF16(o[ngp * 2],     pl, vh0);
                MMA_BF16(o[ngp * 2 + 1], ph, vh1);
                MMA_BF16(o[ngp * 2 + 1], ph, vl1);
                MMA_BF16(o[ngp * 2 + 1], pl, vh1);
            }
        }
    };

    // --- pipelined mainloop (wait counts derived from FIFO group order) ---
    // chunk 0: queue [Q,K0,V0,K1,V1]
    CP_WAIT(3); __syncthreads();          // Q, K0 ready (mask visible too)
    computeS(OFF_KA);
    __syncthreads(); issueK(2, OFF_KA);   // all warps done reading KA
    CP_WAIT(3); __syncthreads();          // V0 ready
    softmaxPV(0, OFF_VA);
    __syncthreads(); issueV(2, OFF_VA);   // all warps done reading VA
    // chunk 1: queue [K1,V1,K2,V2]
    CP_WAIT(3); __syncthreads();          // K1 ready
    computeS(OFF_KB);
    __syncthreads(); issueK(3, OFF_KB);
    CP_WAIT(3); __syncthreads();          // V1 ready
    softmaxPV(1, OFF_VB);
    __syncthreads(); issueV(3, OFF_VB);
    // chunk 2: queue [K2,V2,K3,V3]
    CP_WAIT(3); __syncthreads();          // K2 ready
    computeS(OFF_KA);
    __syncthreads();
    CP_WAIT(2); __syncthreads();          // V2 ready
    softmaxPV(2, OFF_VA);
    __syncthreads();
    // chunk 3: queue [K3,V3]
    CP_WAIT(1); __syncthreads();          // K3 ready
    computeS(OFF_KB);
    CP_WAIT(0); __syncthreads();          // V3 ready
    softmaxPV(3, OFF_VB);

    // --- normalize + write split bf16 ------------------------------------
    const float inv1 = 1.0f / S1, inv2 = 1.0f / S2;
    const int r1 = wm * 16 + (lane >> 2), r2 = r1 + 8;
    #pragma unroll
    for (int j = 0; j < 8; j++) {
        int col = j * 8 + (lane & 3) * 2;
        size_t go1 = (size_t)(b * SEQ_N + n0 + r1) * DIM + h * HD + col;
        size_t go2 = (size_t)(b * SEQ_N + n0 + r2) * DIM + h * HD + col;
        uint32_t hh, ll;
        split2(o[j][0] * inv1, o[j][1] * inv1, hh, ll);
        *(uint32_t*)(Oh + go1) = hh; *(uint32_t*)(Ol + go1) = ll;
        split2(o[j][2] * inv2, o[j][3] * inv2, hh, ll);
        *(uint32_t*)(Oh + go2) = hh; *(uint32_t*)(Ol + go2) = ll;
    }
}

// ---------------------------------------------------------------------------
// Host launcher (identical to R10)
// ---------------------------------------------------------------------------
extern "C" void kernel_launch(void* const* d_in, const int* in_sizes, int n_in,
                              void* d_out, int out_size)
{
    const float* x    = (const float*)d_in[0];
    const float* ctx  = (const float*)d_in[1];
    const int*   mask = (const int*)d_in[2];
    const float* Wq   = (const float*)d_in[3];
    const float* Wk   = (const float*)d_in[4];
    const float* Wv   = (const float*)d_in[5];
    const float* Wo   = (const float*)d_in[6];
    float*       out  = (float*)d_out;

    __nv_bfloat16 *Ahp, *Alp, *Chp, *Clp, *Bhp, *Blp, *Qhp, *Qlp, *Khp, *Klp, *Vhp, *Vlp;
    cudaGetSymbolAddress((void**)&Ahp, g_Ah);
    cudaGetSymbolAddress((void**)&Alp, g_Al);
    cudaGetSymbolAddress((void**)&Chp, g_Ch);
    cudaGetSymbolAddress((void**)&Clp, g_Cl);
    cudaGetSymbolAddress((void**)&Bhp, g_Bh);
    cudaGetSymbolAddress((void**)&Blp, g_Bl);
    cudaGetSymbolAddress((void**)&Qhp, g_Qh);
    cudaGetSymbolAddress((void**)&Qlp, g_Ql);
    cudaGetSymbolAddress((void**)&Khp, g_Kh);
    cudaGetSymbolAddress((void**)&Klp, g_Kl);
    cudaGetSymbolAddress((void**)&Vhp, g_Vh);
    cudaGetSymbolAddress((void**)&Vlp, g_Vl);

    cudaFuncSetAttribute(gemm_hmma_kernel<0>, cudaFuncAttributeMaxDynamicSharedMemorySize, GEMM_SMEM);
    cudaFuncSetAttribute(gemm_hmma_kernel<1>, cudaFuncAttributeMaxDynamicSharedMemorySize, GEMM_SMEM);
    cudaFuncSetAttribute(attn_hmma_kernel, cudaFuncAttributeMaxDynamicSharedMemorySize, ATTN_SMEM);

    const int n4x = ROWS_X * DIM / 4;
    const int n4c = ROWS_C * CTX_DIM / 4;
    dim3 tb32(32, 8);

    // Q projection -> split bf16
    split_kernel<<<n4x / 256, 256>>>(x, Ahp, Alp, n4x);
    transpose_split_kernel<<<dim3(DIM / 32, DIM / 32), tb32>>>(Wq, Bhp, Blp, DIM, DIM);
    gemm_hmma_kernel<1><<<dim3(DIM / BN, ROWS_X / BM), 256, GEMM_SMEM>>>(
        Ahp, Alp, Bhp, Blp, nullptr, Qhp, Qlp, nullptr, nullptr, DIM);

    // fused K|V projection -> split bf16
    split_kernel<<<n4c / 256, 256>>>(ctx, Chp, Clp, n4c);
    transpose_split_kernel<<<dim3(DIM / 32, CTX_DIM / 32), tb32>>>(Wk, Bhp, Blp, CTX_DIM, DIM);
    transpose_split_kernel<<<dim3(DIM / 32, CTX_DIM / 32), tb32>>>(
        Wv, Bhp + 1024 * CTX_DIM, Blp + 1024 * CTX_DIM, CTX_DIM, DIM);
    gemm_hmma_kernel<1><<<dim3(2048 / BN, ROWS_C / BM), 256, GEMM_SMEM>>>(
        Chp, Clp, Bhp, Blp, nullptr, Khp, Klp, Vhp, Vlp, CTX_DIM);

    // Flash attention -> split bf16 into g_Ah/g_Al
    attn_hmma_kernel<<<dim3(SEQ_N / 128, BATCH * HEADS), 256, ATTN_SMEM>>>(
        Qhp, Qlp, Khp, Klp, Vhp, Vlp, mask, Ahp, Alp);

    // O projection -> fp32 final output
    transpose_split_kernel<<<dim3(DIM / 32, DIM / 32), tb32>>>(Wo, Bhp, Blp, DIM, DIM);
    gemm_hmma_kernel<0><<<dim3(DIM / BN, ROWS_X / BM), 256, GEMM_SMEM>>>(
        Ahp, Alp, Bhp, Blp, out, nullptr, nullptr, nullptr, nullptr, DIM);
}

// round 12
// speedup vs baseline: 1.3151x; 1.0198x over previous
#include <cuda_runtime.h>
#include <cuda_bf16.h>
#include <math.h>
#include <stdint.h>

// Problem constants
#define BATCH 4
#define SEQ_N 4096
#define SEQ_M 256
#define DIM 1024
#define CTX_DIM 768
#define HEADS 16
#define HD 64
#define ROWS_X (BATCH * SEQ_N)      // 16384
#define ROWS_C (BATCH * SEQ_M)      // 1024

// Scratch (device globals)
__device__ __nv_bfloat16 g_Ah[ROWS_X * DIM];
__device__ __nv_bfloat16 g_Al[ROWS_X * DIM];
__device__ __nv_bfloat16 g_Ch[ROWS_C * CTX_DIM];
__device__ __nv_bfloat16 g_Cl[ROWS_C * CTX_DIM];
__device__ __nv_bfloat16 g_Bqh[DIM * DIM];      // Wq^T
__device__ __nv_bfloat16 g_Bql[DIM * DIM];
__device__ __nv_bfloat16 g_Bh[2048 * 1024];     // [Wk^T ; Wv^T]
__device__ __nv_bfloat16 g_Bl[2048 * 1024];
__device__ __nv_bfloat16 g_Boh[DIM * DIM];      // Wo^T
__device__ __nv_bfloat16 g_Bol[DIM * DIM];
__device__ __nv_bfloat16 g_Qh[ROWS_X * DIM];
__device__ __nv_bfloat16 g_Ql[ROWS_X * DIM];
__device__ __nv_bfloat16 g_Kh[ROWS_C * DIM];
__device__ __nv_bfloat16 g_Kl[ROWS_C * DIM];
__device__ __nv_bfloat16 g_Vh[ROWS_C * DIM];
__device__ __nv_bfloat16 g_Vl[ROWS_C * DIM];

// ---------------------------------------------------------------------------
// PTX helpers (sm_80+ portable)
// ---------------------------------------------------------------------------
__device__ __forceinline__ uint32_t smem_u32(const void* p) {
    uint32_t a;
    asm("{ .reg .u64 t; cvta.to.shared.u64 t, %1; cvt.u32.u64 %0, t; }" : "=r"(a) : "l"(p));
    return a;
}
#define CP_ASYNC16(dst, src) \
    asm volatile("cp.async.cg.shared.global [%0], [%1], 16;" :: "r"(dst), "l"(src))
#define CP_COMMIT() asm volatile("cp.async.commit_group;" ::: "memory")
#define CP_WAIT(n)  asm volatile("cp.async.wait_group %0;" :: "n"(n) : "memory")

#define LDM_X4(r0, r1, r2, r3, a) \
    asm volatile("ldmatrix.sync.aligned.m8n8.x4.shared.b16 {%0,%1,%2,%3}, [%4];" \
                 : "=r"(r0), "=r"(r1), "=r"(r2), "=r"(r3) : "r"(a))
#define LDM_X4T(r0, r1, r2, r3, a) \
    asm volatile("ldmatrix.sync.aligned.m8n8.x4.trans.shared.b16 {%0,%1,%2,%3}, [%4];" \
                 : "=r"(r0), "=r"(r1), "=r"(r2), "=r"(r3) : "r"(a))

#define MMA_BF16(d, a, b) \
    asm volatile("mma.sync.aligned.m16n8k16.row.col.f32.bf16.bf16.f32 " \
                 "{%0,%1,%2,%3},{%4,%5,%6,%7},{%8,%9},{%0,%1,%2,%3};" \
                 : "+f"((d)[0]), "+f"((d)[1]), "+f"((d)[2]), "+f"((d)[3]) \
                 : "r"((a)[0]), "r"((a)[1]), "r"((a)[2]), "r"((a)[3]), \
                   "r"((b)[0]), "r"((b)[1]))

__device__ __forceinline__ void split2(float x, float y, uint32_t& h, uint32_t& l) {
    __nv_bfloat162 hb = __float22bfloat162_rn(make_float2(x, y));
    float2 hf = __bfloat1622float2(hb);
    __nv_bfloat162 lb = __float22bfloat162_rn(make_float2(x - hf.x, y - hf.y));
    h = *(uint32_t*)&hb;
    l = *(uint32_t*)&lb;
}

// ---------------------------------------------------------------------------
// fp32 -> bf16 hi/lo split
// ---------------------------------------------------------------------------
__global__ void split_kernel(const float* __restrict__ X, __nv_bfloat16* __restrict__ Xh,
                             __nv_bfloat16* __restrict__ Xl, int n4)
{
    int i = blockIdx.x * blockDim.x + threadIdx.x;
    if (i >= n4) return;
    float4 v = ((const float4*)X)[i];
    float a[4] = {v.x, v.y, v.z, v.w};
    __nv_bfloat16 h[4], l[4];
    #pragma unroll
    for (int j = 0; j < 4; j++) {
        h[j] = __float2bfloat16(a[j]);
        l[j] = __float2bfloat16(a[j] - __bfloat162float(h[j]));
    }
    __nv_bfloat162* Hp = (__nv_bfloat162*)(Xh + 4 * (size_t)i);
    __nv_bfloat162* Lp = (__nv_bfloat162*)(Xl + 4 * (size_t)i);
    Hp[0] = __nv_bfloat162(h[0], h[1]); Hp[1] = __nv_bfloat162(h[2], h[3]);
    Lp[0] = __nv_bfloat162(l[0], l[1]); Lp[1] = __nv_bfloat162(l[2], l[3]);
}

// ---------------------------------------------------------------------------
// W[K][N] -> Th/Tl[N][K] bf16 hi/lo (transpose + split)
// ---------------------------------------------------------------------------
__global__ void transpose_split_kernel(const float* __restrict__ W, __nv_bfloat16* __restrict__ Th,
                                       __nv_bfloat16* __restrict__ Tl, int K, int N)
{
    __shared__ float tile[32][33];
    int n0 = blockIdx.x * 32, k0 = blockIdx.y * 32;
    int tx = threadIdx.x, ty = threadIdx.y;
    #pragma unroll
    for (int j = ty; j < 32; j += 8)
        tile[j][tx] = W[(size_t)(k0 + j) * N + n0 + tx];
    __syncthreads();
    #pragma unroll
    for (int j = ty; j < 32; j += 8) {
        float v = tile[tx][j];
        __nv_bfloat16 h = __float2bfloat16(v);
        __nv_bfloat16 l = __float2bfloat16(v - __bfloat162float(h));
        size_t o = (size_t)(n0 + j) * K + k0 + tx;
        Th[o] = h; Tl[o] = l;
    }
}

// ---------------------------------------------------------------------------
// HMMA bf16-split GEMM (R10-proven): 128x128x32 CTA tile, 8 warps of 64x32,
// 2-stage cp.async double buffer, 2 CTAs/SM. SPLIT=0: fp32 out. SPLIT=1:
// bf16 hi/lo out; cols >= 1024 routed to D pair (fused K|V projection).
// ---------------------------------------------------------------------------
#define BM 128
#define BN 128
#define BK 32
#define PITCH 80
#define TILE_B (128 * PITCH)        // 10240
#define STAGE  (4 * TILE_B)         // 40960
#define GEMM_SMEM (2 * STAGE)       // 81920

template<int SPLIT>
__global__ void __launch_bounds__(256, 2)
gemm_hmma_kernel(const __nv_bfloat16* __restrict__ Ah, const __nv_bfloat16* __restrict__ Al,
                 const __nv_bfloat16* __restrict__ Bh, const __nv_bfloat16* __restrict__ Bl,
                 float* __restrict__ C, __nv_bfloat16* __restrict__ Ch,
                 __nv_bfloat16* __restrict__ Cl, __nv_bfloat16* __restrict__ Dh,
                 __nv_bfloat16* __restrict__ Dl, int K)
{
    extern __shared__ __align__(128) char sm[];
    const uint32_t sb = smem_u32(sm);
    const int t = threadIdx.x, wid = t >> 5, lane = t & 31;
    const int m0 = blockIdx.y * BM, n0 = blockIdx.x * BN;
    const int NC = K / BK;
    const int wr = wid & 1, wc = wid >> 1;

    const int lr0 = t >> 2;
    const int lch = t & 3;

    const int g = lane >> 3, lrw = lane & 7;
    const uint32_t a_off = (uint32_t)(((g & 1) * 8 + lrw) * PITCH + (g >> 1) * 16);
    const uint32_t b_off = (uint32_t)(((g >> 1) * 8 + lrw) * PITCH + (g & 1) * 16);

    float acc[4][4][4];
    #pragma unroll
    for (int mt = 0; mt < 4; mt++)
        #pragma unroll
        for (int ng = 0; ng < 4; ng++)
            #pragma unroll
            for (int q = 0; q < 4; q++) acc[mt][ng][q] = 0.0f;

    auto issue = [&](int c) {
        const int buf = c & 1;
        const uint32_t stg = sb + buf * STAGE;
        const int kt = c * BK;
        #pragma unroll
        for (int i = 0; i < 2; i++) {
            const int r = lr0 + i * 64;
            const uint32_t doff = (uint32_t)(r * PITCH + lch * 16);
            const size_t sa = (size_t)(m0 + r) * K + kt + lch * 8;
            const size_t sbi = (size_t)(n0 + r) * K + kt + lch * 8;
            CP_ASYNC16(stg + doff,               Ah + sa);
            CP_ASYNC16(stg + TILE_B + doff,      Al + sa);
            CP_ASYNC16(stg + 2 * TILE_B + doff,  Bh + sbi);
            CP_ASYNC16(stg + 3 * TILE_B + doff,  Bl + sbi);
        }
        CP_COMMIT();
    };

    issue(0);

    for (int c = 0; c < NC; c++) {
        if (c + 1 < NC) { issue(c + 1); CP_WAIT(1); }
        else            { CP_WAIT(0); }
        __syncthreads();

        const uint32_t stg = sb + (c & 1) * STAGE;
        const uint32_t aH = stg + (uint32_t)(wr * 64) * PITCH;
        const uint32_t aL = aH + TILE_B;
        const uint32_t bH = stg + 2 * TILE_B + (uint32_t)(wc * 32) * PITCH;
        const uint32_t bL = bH + TILE_B;

        #pragma unroll
        for (int ks = 0; ks < 2; ks++) {
            const uint32_t kb = (uint32_t)(ks * 32);
            uint32_t fAh[4][4], fAl[4][4], fBh[4][2], fBl[4][2];
            #pragma unroll
            for (int mt = 0; mt < 4; mt++) {
                uint32_t ad = aH + (uint32_t)(mt * 16) * PITCH + kb + a_off;
                LDM_X4(fAh[mt][0], fAh[mt][1], fAh[mt][2], fAh[mt][3], ad);
                uint32_t ad2 = aL + (uint32_t)(mt * 16) * PITCH + kb + a_off;
                LDM_X4(fAl[mt][0], fAl[mt][1], fAl[mt][2], fAl[mt][3], ad2);
            }
            #pragma unroll
            for (int nt = 0; nt < 2; nt++) {
                uint32_t bd = bH + (uint32_t)(nt * 16) * PITCH + kb + b_off;
                uint32_t r0, r1, r2, r3;
                LDM_X4(r0, r1, r2, r3, bd);
                fBh[nt * 2][0] = r0; fBh[nt * 2][1] = r1;
                fBh[nt * 2 + 1][0] = r2; fBh[nt * 2 + 1][1] = r3;
                uint32_t bd2 = bL + (uint32_t)(nt * 16) * PITCH + kb + b_off;
                LDM_X4(r0, r1, r2, r3, bd2);
                fBl[nt * 2][0] = r0; fBl[nt * 2][1] = r1;
                fBl[nt * 2 + 1][0] = r2; fBl[nt * 2 + 1][1] = r3;
            }
            #pragma unroll
            for (int mt = 0; mt < 4; mt++) {
                #pragma unroll
                for (int ng = 0; ng < 4; ng++) {
                    MMA_BF16(acc[mt][ng], fAh[mt], fBh[ng]);
                    MMA_BF16(acc[mt][ng], fAh[mt], fBl[ng]);
                    MMA_BF16(acc[mt][ng], fAl[mt], fBh[ng]);
                }
            }
        }
        __syncthreads();
    }

    const int row0 = m0 + wr * 64 + lane / 4;
    const int col0 = wc * 32 + (lane % 4) * 2;
    #pragma unroll
    for (int mt = 0; mt < 4; mt++) {
        #pragma unroll
        for (int ng = 0; ng < 4; ng++) {
            int gc = n0 + col0 + ng * 8;
            if (SPLIT) {
                __nv_bfloat16 *Hp, *Lp;
                if (gc < 1024) { Hp = Ch; Lp = Cl; }
                else           { Hp = Dh; Lp = Dl; gc -= 1024; }
                size_t o1 = (size_t)(row0 + mt * 16) * DIM + gc;
                size_t o2 = o1 + 8 * DIM;
                uint32_t h, l;
                split2(acc[mt][ng][0], acc[mt][ng][1], h, l);
                *(uint32_t*)(Hp + o1) = h; *(uint32_t*)(Lp + o1) = l;
                split2(acc[mt][ng][2], acc[mt][ng][3], h, l);
                *(uint32_t*)(Hp + o2) = h; *(uint32_t*)(Lp + o2) = l;
            } else {
                size_t o1 = (size_t)(row0 + mt * 16) * DIM + gc;
                size_t o2 = o1 + 8 * DIM;
                *(float2*)(C + o1) = make_float2(acc[mt][ng][0], acc[mt][ng][1]);
                *(float2*)(C + o2) = make_float2(acc[mt][ng][2], acc[mt][ng][3]);
            }
        }
    }
}

// ---------------------------------------------------------------------------
// HMMA flash-attention (R11-proven): 128 Q-rows/CTA, chunked 2-CTA/SM online
// softmax pipeline; four 64-key chunks, double-buffered K/V, cp.async pacing.
// ---------------------------------------------------------------------------
#define AP 144
#define OFF_QH 0
#define OFF_QL 18432
#define OFF_KA 36864
#define OFF_KB 55296
#define OFF_VA 73728
#define OFF_VB 92160
#define OFF_MS 110592
#define ATTN_SMEM 111616
#define KHALF 9216

__global__ void __launch_bounds__(256, 2)
attn_hmma_kernel(const __nv_bfloat16* __restrict__ Qh, const __nv_bfloat16* __restrict__ Ql,
                 const __nv_bfloat16* __restrict__ Kh, const __nv_bfloat16* __restrict__ Kl,
                 const __nv_bfloat16* __restrict__ Vh, const __nv_bfloat16* __restrict__ Vl,
                 const int* __restrict__ maskp,
                 __nv_bfloat16* __restrict__ Oh, __nv_bfloat16* __restrict__ Ol)
{
    extern __shared__ __align__(128) char smc[];
    const uint32_t sb = smem_u32(smc);
    int* Msm = (int*)(smc + OFF_MS);

    const int t = threadIdx.x, wid = t >> 5, lane = t & 31;
    const int b = blockIdx.y >> 4, h = blockIdx.y & 15;
    const int n0 = blockIdx.x * 128;

    auto issueQ = [&]() {
        #pragma unroll
        for (int i = 0; i < 4; i++) {
            int idx = t + i * 256;
            int r = idx >> 3, ch = idx & 7;
            uint32_t doff = (uint32_t)(r * AP + ch * 16);
            size_t src = (size_t)(b * SEQ_N + n0 + r) * DIM + h * HD + ch * 8;
            CP_ASYNC16(sb + OFF_QH + doff, Qh + src);
            CP_ASYNC16(sb + OFF_QL + doff, Ql + src);
        }
        CP_COMMIT();
    };
    auto issueK = [&](int c, uint32_t off) {
        #pragma unroll
        for (int i = 0; i < 2; i++) {
            int idx = t + i * 256;
            int r = idx >> 3, ch = idx & 7;
            uint32_t doff = (uint32_t)(r * AP + ch * 16);
            size_t src = (size_t)(b * SEQ_M + c * 64 + r) * DIM + h * HD + ch * 8;
            CP_ASYNC16(sb + off + doff,         Kh + src);
            CP_ASYNC16(sb + off + KHALF + doff, Kl + src);
        }
        CP_COMMIT();
    };
    auto issueV = [&](int c, uint32_t off) {
        #pragma unroll
        for (int i = 0; i < 2; i++) {
            int idx = t + i * 256;
            int r = idx >> 3, ch = idx & 7;
            uint32_t doff = (uint32_t)(r * AP + ch * 16);
            size_t src = (size_t)(b * SEQ_M + c * 64 + r) * DIM + h * HD + ch * 8;
            CP_ASYNC16(sb + off + doff,         Vh + src);
            CP_ASYNC16(sb + off + KHALF + doff, Vl + src);
        }
        CP_COMMIT();
    };

    issueQ();
    issueK(0, OFF_KA); issueV(0, OFF_VA);
    issueK(1, OFF_KB); issueV(1, OFF_VB);
    Msm[t] = maskp[b * SEQ_M + t];

    const int wm = wid;
    const int g = lane >> 3, lrw = lane & 7;
    const uint32_t a_off = (uint32_t)(((g & 1) * 8 + lrw) * AP + (g >> 1) * 16);
    const uint32_t b_off = (uint32_t)(((g >> 1) * 8 + lrw) * AP + (g & 1) * 16);

    float o[8][4];
    #pragma unroll
    for (int j = 0; j < 8; j++)
        #pragma unroll
        for (int q = 0; q < 4; q++) o[j][q] = 0.0f;
    float M1 = -INFINITY, M2 = -INFINITY, S1 = 0.0f, S2 = 0.0f;
    float acc[8][4];
    const float scale = 0.125f;

    auto computeS = [&](uint32_t ko) {
        #pragma unroll
        for (int j = 0; j < 8; j++)
            #pragma unroll
            for (int q = 0; q < 4; q++) acc[j][q] = 0.0f;
        #pragma unroll
        for (int ks = 0; ks < 4; ks++) {
            const uint32_t kb = (uint32_t)(ks * 32);
            uint32_t fAh[4], fAl[4];
            LDM_X4(fAh[0], fAh[1], fAh[2], fAh[3],
                   sb + OFF_QH + (uint32_t)(wm * 16) * AP + kb + a_off);
            LDM_X4(fAl[0], fAl[1], fAl[2], fAl[3],
                   sb + OFF_QL + (uint32_t)(wm * 16) * AP + kb + a_off);
            #pragma unroll
            for (int nt = 0; nt < 4; nt++) {
                uint32_t krow = (uint32_t)(nt * 16) * AP + kb + b_off;
                uint32_t h0, h1, h2, h3, l0, l1, l2, l3;
                LDM_X4(h0, h1, h2, h3, sb + ko + krow);
                LDM_X4(l0, l1, l2, l3, sb + ko + KHALF + krow);
                uint32_t bh0[2] = {h0, h1}, bh1[2] = {h2, h3};
                uint32_t bl0[2] = {l0, l1}, bl1[2] = {l2, l3};
                MMA_BF16(acc[nt * 2],     fAh, bh0);
                MMA_BF16(acc[nt * 2],     fAh, bl0);
                MMA_BF16(acc[nt * 2],     fAl, bh0);
                MMA_BF16(acc[nt * 2 + 1], fAh, bh1);
                MMA_BF16(acc[nt * 2 + 1], fAh, bl1);
                MMA_BF16(acc[nt * 2 + 1], fAl, bh1);
            }
        }
    };

    auto softmaxPV = [&](int ci, uint32_t vo) {
        float m1 = -INFINITY, m2 = -INFINITY;
        #pragma unroll
        for (int j = 0; j < 8; j++) {
            int cb = ci * 64 + j * 8 + (lane & 3) * 2;
            bool k0 = Msm[cb] != 0, k1 = Msm[cb + 1] != 0;
            acc[j][0] = k0 ? acc[j][0] * scale : -1e30f;
            acc[j][1] = k1 ? acc[j][1] * scale : -1e30f;
            acc[j][2] = k0 ? acc[j][2] * scale : -1e30f;
            acc[j][3] = k1 ? acc[j][3] * scale : -1e30f;
            m1 = fmaxf(m1, fmaxf(acc[j][0], acc[j][1]));
            m2 = fmaxf(m2, fmaxf(acc[j][2], acc[j][3]));
        }
        m1 = fmaxf(m1, __shfl_xor_sync(0xffffffffu, m1, 1));
        m1 = fmaxf(m1, __shfl_xor_sync(0xffffffffu, m1, 2));
        m2 = fmaxf(m2, __shfl_xor_sync(0xffffffffu, m2, 1));
        m2 = fmaxf(m2, __shfl_xor_sync(0xffffffffu, m2, 2));

        float M1n = fmaxf(M1, m1), M2n = fmaxf(M2, m2);
        float sc1 = __expf(M1 - M1n), sc2 = __expf(M2 - M2n);
        #pragma unroll
        for (int j = 0; j < 8; j++) {
            o[j][0] *= sc1; o[j][1] *= sc1;
            o[j][2] *= sc2; o[j][3] *= sc2;
        }
        S1 *= sc1; S2 *= sc2;
        M1 = M1n; M2 = M2n;

        float s1 = 0.0f, s2 = 0.0f;
        #pragma unroll
        for (int j = 0; j < 8; j++) {
            acc[j][0] = __expf(acc[j][0] - M1);
            acc[j][1] = __expf(acc[j][1] - M1);
            acc[j][2] = __expf(acc[j][2] - M2);
            acc[j][3] = __expf(acc[j][3] - M2);
            s1 += acc[j][0] + acc[j][1];
            s2 += acc[j][2] + acc[j][3];
        }
        s1 += __shfl_xor_sync(0xffffffffu, s1, 1);
        s1 += __shfl_xor_sync(0xffffffffu, s1, 2);
        s2 += __shfl_xor_sync(0xffffffffu, s2, 1);
        s2 += __shfl_xor_sync(0xffffffffu, s2, 2);
        S1 += s1; S2 += s2;

        #pragma unroll
        for (int kk = 0; kk < 4; kk++) {
            const int j0 = kk * 2, j1 = j0 + 1;
            uint32_t ph[4], pl[4];
            split2(acc[j0][0], acc[j0][1], ph[0], pl[0]);
            split2(acc[j0][2], acc[j0][3], ph[1], pl[1]);
            split2(acc[j1][0], acc[j1][1], ph[2], pl[2]);
            split2(acc[j1][2], acc[j1][3], ph[3], pl[3]);

            const uint32_t vrow = (uint32_t)(kk * 16 + (g & 1) * 8 + lrw) * AP;
            #pragma unroll
            for (int ngp = 0; ngp < 4; ngp++) {
                const uint32_t vcol = (uint32_t)(((g >> 1) * 8 + ngp * 16) * 2);
                uint32_t h0, h1, h2, h3, l0, l1, l2, l3;
                LDM_X4T(h0, h1, h2, h3, sb + vo + vrow + vcol);
                LDM_X4T(l0, l1, l2, l3, sb + vo + KHALF + vrow + vcol);
                uint32_t vh0[2] = {h0, h1}, vh1[2] = {h2, h3};
                uint32_t vl0[2] = {l0, l1}, vl1[2] = {l2, l3};
                MMA_BF16(o[ngp * 2],     ph, vh0);
                MMA_BF16(o[ngp * 2],     ph, vl0);
                MMA_BF16(o[ngp * 2],     pl, vh0);
                MMA_BF16(o[ngp * 2 + 1], ph, vh1);
                MMA_BF16(o[ngp * 2 + 1], ph, vl1);
                MMA_BF16(o[ngp * 2 + 1], pl, vh1);
            }
        }
    };

    CP_WAIT(3); __syncthreads();
    computeS(OFF_KA);
    __syncthreads(); issueK(2, OFF_KA);
    CP_WAIT(3); __syncthreads();
    softmaxPV(0, OFF_VA);
    __syncthreads(); issueV(2, OFF_VA);
    CP_WAIT(3); __syncthreads();
    computeS(OFF_KB);
    __syncthreads(); issueK(3, OFF_KB);
    CP_WAIT(3); __syncthreads();
    softmaxPV(1, OFF_VB);
    __syncthreads(); issueV(3, OFF_VB);
    CP_WAIT(3); __syncthreads();
    computeS(OFF_KA);
    __syncthreads();
    CP_WAIT(2); __syncthreads();
    softmaxPV(2, OFF_VA);
    __syncthreads();
    CP_WAIT(1); __syncthreads();
    computeS(OFF_KB);
    CP_WAIT(0); __syncthreads();
    softmaxPV(3, OFF_VB);

    const float inv1 = 1.0f / S1, inv2 = 1.0f / S2;
    const int r1 = wm * 16 + (lane >> 2), r2 = r1 + 8;
    #pragma unroll
    for (int j = 0; j < 8; j++) {
        int col = j * 8 + (lane & 3) * 2;
        size_t go1 = (size_t)(b * SEQ_N + n0 + r1) * DIM + h * HD + col;
        size_t go2 = (size_t)(b * SEQ_N + n0 + r2) * DIM + h * HD + col;
        uint32_t hh, ll;
        split2(o[j][0] * inv1, o[j][1] * inv1, hh, ll);
        *(uint32_t*)(Oh + go1) = hh; *(uint32_t*)(Ol + go1) = ll;
        split2(o[j][2] * inv2, o[j][3] * inv2, hh, ll);
        *(uint32_t*)(Oh + go2) = hh; *(uint32_t*)(Ol + go2) = ll;
    }
}

// ---------------------------------------------------------------------------
// Host launcher — two-stream fork/join (streams+events created on the first,
// uncaptured call; nothing is created during graph capture).
// ---------------------------------------------------------------------------
extern "C" void kernel_launch(void* const* d_in, const int* in_sizes, int n_in,
                              void* d_out, int out_size)
{
    const float* x    = (const float*)d_in[0];
    const float* ctx  = (const float*)d_in[1];
    const int*   mask = (const int*)d_in[2];
    const float* Wq   = (const float*)d_in[3];
    const float* Wk   = (const float*)d_in[4];
    const float* Wv   = (const float*)d_in[5];
    const float* Wo   = (const float*)d_in[6];
    float*       out  = (float*)d_out;

    __nv_bfloat16 *Ahp, *Alp, *Chp, *Clp, *Bqh, *Bql, *Bhp, *Blp, *Boh, *Bol;
    __nv_bfloat16 *Qhp, *Qlp, *Khp, *Klp, *Vhp, *Vlp;
    cudaGetSymbolAddress((void**)&Ahp, g_Ah);
    cudaGetSymbolAddress((void**)&Alp, g_Al);
    cudaGetSymbolAddress((void**)&Chp, g_Ch);
    cudaGetSymbolAddress((void**)&Clp, g_Cl);
    cudaGetSymbolAddress((void**)&Bqh, g_Bqh);
    cudaGetSymbolAddress((void**)&Bql, g_Bql);
    cudaGetSymbolAddress((void**)&Bhp, g_Bh);
    cudaGetSymbolAddress((void**)&Blp, g_Bl);
    cudaGetSymbolAddress((void**)&Boh, g_Boh);
    cudaGetSymbolAddress((void**)&Bol, g_Bol);
    cudaGetSymbolAddress((void**)&Qhp, g_Qh);
    cudaGetSymbolAddress((void**)&Qlp, g_Ql);
    cudaGetSymbolAddress((void**)&Khp, g_Kh);
    cudaGetSymbolAddress((void**)&Klp, g_Kl);
    cudaGetSymbolAddress((void**)&Vhp, g_Vh);
    cudaGetSymbolAddress((void**)&Vlp, g_Vl);

    cudaFuncSetAttribute(gemm_hmma_kernel<0>, cudaFuncAttributeMaxDynamicSharedMemorySize, GEMM_SMEM);
    cudaFuncSetAttribute(gemm_hmma_kernel<1>, cudaFuncAttributeMaxDynamicSharedMemorySize, GEMM_SMEM);
    cudaFuncSetAttribute(attn_hmma_kernel, cudaFuncAttributeMaxDynamicSharedMemorySize, ATTN_SMEM);

    // One-time resource creation (first call is the uncaptured correctness run)
    static cudaStream_t s_aux = nullptr;
    static cudaEvent_t ev_fork = nullptr, ev_wq = nullptr, ev_kv = nullptr, ev_wo = nullptr;
    if (s_aux == nullptr) {
        cudaStreamCreateWithFlags(&s_aux, cudaStreamNonBlocking);
        cudaEventCreateWithFlags(&ev_fork, cudaEventDisableTiming);
        cudaEventCreateWithFlags(&ev_wq,   cudaEventDisableTiming);
        cudaEventCreateWithFlags(&ev_kv,   cudaEventDisableTiming);
        cudaEventCreateWithFlags(&ev_wo,   cudaEventDisableTiming);
    }

    const int n4x = ROWS_X * DIM / 4;
    const int n4c = ROWS_C * CTX_DIM / 4;
    dim3 tb32(32, 8);

    // Fork aux stream off the main (legacy default) stream
    cudaEventRecord(ev_fork, 0);
    cudaStreamWaitEvent(s_aux, ev_fork, 0);

    // aux: Wq^T first (Q-proj needs it), then KV chain, then Wo^T
    transpose_split_kernel<<<dim3(DIM / 32, DIM / 32), tb32, 0, s_aux>>>(Wq, Bqh, Bql, DIM, DIM);
    cudaEventRecord(ev_wq, s_aux);
    split_kernel<<<n4c / 256, 256, 0, s_aux>>>(ctx, Chp, Clp, n4c);
    transpose_split_kernel<<<dim3(DIM / 32, CTX_DIM / 32), tb32, 0, s_aux>>>(Wk, Bhp, Blp, CTX_DIM, DIM);
    transpose_split_kernel<<<dim3(DIM / 32, CTX_DIM / 32), tb32, 0, s_aux>>>(
        Wv, Bhp + 1024 * CTX_DIM, Blp + 1024 * CTX_DIM, CTX_DIM, DIM);
    gemm_hmma_kernel<1><<<dim3(2048 / BN, ROWS_C / BM), 256, GEMM_SMEM, s_aux>>>(
        Chp, Clp, Bhp, Blp, nullptr, Khp, Klp, Vhp, Vlp, CTX_DIM);
    cudaEventRecord(ev_kv, s_aux);
    transpose_split_kernel<<<dim3(DIM / 32, DIM / 32), tb32, 0, s_aux>>>(Wo, Boh, Bol, DIM, DIM);
    cudaEventRecord(ev_wo, s_aux);

    // main: split x, Q projection (after Wq^T), attention (after KV), O proj (after Wo^T)
    split_kernel<<<n4x / 256, 256>>>(x, Ahp, Alp, n4x);
    cudaStreamWaitEvent(0, ev_wq, 0);
    gemm_hmma_kernel<1><<<dim3(DIM / BN, ROWS_X / BM), 256, GEMM_SMEM>>>(
        Ahp, Alp, Bqh, Bql, nullptr, Qhp, Qlp, nullptr, nullptr, DIM);

    cudaStreamWaitEvent(0, ev_kv, 0);
    attn_hmma_kernel<<<dim3(SEQ_N / 128, BATCH * HEADS), 256, ATTN_SMEM>>>(
        Qhp, Qlp, Khp, Klp, Vhp, Vlp, mask, Ahp, Alp);

    cudaStreamWaitEvent(0, ev_wo, 0);
    gemm_hmma_kernel<0><<<dim3(DIM / BN, ROWS_X / BM), 256, GEMM_SMEM>>>(
        Ahp, Alp, Boh, Bol, out, nullptr, nullptr, nullptr, nullptr, DIM);
}